// round 8
// baseline (speedup 1.0000x reference)
#include <cuda_runtime.h>
#include <math.h>

// Problem constants
#define S_ 128
#define B_ 64
#define V_ 10000
#define E_ 256
#define H_ 512

// Fused kernel config
#define NB 64            // recurrence CTAs (1/SM, co-resident)
#define NCTA 148         // total CTAs
#define TPB 512
#define NTN 79           // logits n-tiles
#define NTM 64           // logits m-tiles

// ---------------- device scratch ----------------
// State is [b][k] row-major so threads stream their own batch row.
__device__ float g_h0[2][B_ * H_];
__device__ float g_h1[2][B_ * H_];
__device__ float g_rh0[B_ * H_];
__device__ float g_rh1[B_ * H_];
__device__ float g_Xp[3u * S_ * B_ * H_];    // [gate][t*B+b][k]
__device__ float g_H1[(size_t)S_ * B_ * H_]; // [t*B+b][k]
__device__ unsigned g_bar_count = 0;
__device__ unsigned g_genv[16 * 32];
__device__ int g_progress;
__device__ int g_tile_ctr;

// ---------------- packed f32x2 + cv-load helpers ----------------
__device__ __forceinline__ void fma2(unsigned long long& acc, unsigned long long a,
                                     unsigned long long w) {
    asm("fma.rn.f32x2 %0, %1, %2, %0;" : "+l"(acc) : "l"(a), "l"(w));
}
__device__ __forceinline__ float unpack_sum(unsigned long long v) {
    return __uint_as_float((unsigned)v) + __uint_as_float((unsigned)(v >> 32));
}
__device__ __forceinline__ unsigned long long dup2(float f) {
    unsigned long long d;
    asm("mov.b64 %0, {%1, %1};" : "=l"(d) : "r"(__float_as_uint(f)));
    return d;
}
__device__ __forceinline__ void ld_cv_16(const float* p, unsigned long long& a,
                                         unsigned long long& b) {
    asm volatile("ld.global.cv.v2.u64 {%0,%1}, [%2];" : "=l"(a), "=l"(b) : "l"(p));
}
__device__ __forceinline__ float ld_cv_f(const float* p) {
    float v; asm volatile("ld.global.cv.f32 %0, [%1];" : "=f"(v) : "l"(p)); return v;
}
__device__ __forceinline__ float sigmoidf_(float x) { return 1.0f / (1.0f + expf(-x)); }

// ---------------- grid barrier (NB recurrence CTAs only) ----------------
__device__ __forceinline__ void grid_barrier() {
    __syncthreads();
    if (threadIdx.x == 0) {
        __threadfence();
        unsigned slot = (blockIdx.x & 15) * 32;
        unsigned old = *((volatile unsigned*)&g_genv[slot]);
        unsigned t = atomicAdd(&g_bar_count, 1u);
        if (t == NB - 1) {
            g_bar_count = 0;
            __threadfence();
            #pragma unroll
            for (int i = 0; i < 16; i++)
                *((volatile unsigned*)&g_genv[i * 32]) = old + 1;
        } else {
            while (*((volatile unsigned*)&g_genv[slot]) == old) { }
        }
        __threadfence();
    }
    __syncthreads();
}

// ---------------- recurrence smem layout (weights only) ----------------
#define W0ROW 516
#define W1ROW 1028
#define W0GATE (8 * W0ROW)
#define W1GATE (8 * W1ROW)
#define SM_W1 (3 * W0GATE)
#define SM_FLOATS (SM_W1 + 3 * W1GATE)       // 37056
#define SMEM_BYTES (SM_FLOATS * 4)           // 148224

// ---------------- straight-line dot products (no syncs, direct global A) --------
__device__ __forceinline__ void dotrz(const float* __restrict__ x,
                                      const float* __restrict__ wr,
                                      const float* __restrict__ wz,
                                      unsigned long long* pr, unsigned long long* pz) {
    #pragma unroll 8
    for (int k = 0; k < H_; k += 4) {
        unsigned long long x0, x1;
        ld_cv_16(x + k, x0, x1);
        ulonglong2 w1 = *(const ulonglong2*)(wr + k);
        ulonglong2 w2 = *(const ulonglong2*)(wz + k);
        fma2(pr[0], x0, w1.x); fma2(pr[1], x1, w1.y);
        fma2(pz[0], x0, w2.x); fma2(pz[1], x1, w2.y);
    }
}
// Fused: one x stream feeds both layer-0 gates and layer-1's h0-half gates.
__device__ __forceinline__ void dotrz4(const float* __restrict__ x,
                                       const float* __restrict__ wr0,
                                       const float* __restrict__ wz0,
                                       const float* __restrict__ wr1,
                                       const float* __restrict__ wz1,
                                       unsigned long long* pr0, unsigned long long* pz0,
                                       unsigned long long* pr1, unsigned long long* pz1) {
    #pragma unroll 8
    for (int k = 0; k < H_; k += 4) {
        unsigned long long x0, x1;
        ld_cv_16(x + k, x0, x1);
        ulonglong2 a = *(const ulonglong2*)(wr0 + k);
        ulonglong2 b = *(const ulonglong2*)(wz0 + k);
        ulonglong2 c = *(const ulonglong2*)(wr1 + k);
        ulonglong2 d = *(const ulonglong2*)(wz1 + k);
        fma2(pr0[0], x0, a.x); fma2(pr0[1], x1, a.y);
        fma2(pz0[0], x0, b.x); fma2(pz0[1], x1, b.y);
        fma2(pr1[0], x0, c.x); fma2(pr1[1], x1, c.y);
        fma2(pz1[0], x0, d.x); fma2(pz1[1], x1, d.y);
    }
}
__device__ __forceinline__ void doth(const float* __restrict__ x,
                                     const float* __restrict__ w,
                                     unsigned long long* p) {
    #pragma unroll 8
    for (int k = 0; k < H_; k += 8) {
        unsigned long long x0, x1, x2, x3;
        ld_cv_16(x + k, x0, x1);
        ld_cv_16(x + k + 4, x2, x3);
        ulonglong2 wa = *(const ulonglong2*)(w + k);
        ulonglong2 wb = *(const ulonglong2*)(w + k + 4);
        fma2(p[0], x0, wa.x); fma2(p[1], x1, wa.y);
        fma2(p[2], x2, wb.x); fma2(p[3], x3, wb.y);
    }
}

// ---------------- init / finalize ----------------
__global__ void init_hidden_kernel(const float* __restrict__ hidden) {
    int i = blockIdx.x * blockDim.x + threadIdx.x;
    if (i < B_ * H_) {
        g_h0[0][i] = hidden[i];                 // [b][k] matches input layout
        g_h1[0][i] = hidden[B_ * H_ + i];
    }
    if (blockIdx.x == 0 && threadIdx.x == 0) {
        g_progress = -1;
        g_tile_ctr = 0;
    }
}
__global__ void write_hidden_kernel(float* __restrict__ out, long long off) {
    int i = blockIdx.x * blockDim.x + threadIdx.x;
    if (i < B_ * H_) {
        out[off + i] = g_h0[0][i];              // parity: final states land in buf 0
        out[off + B_ * H_ + i] = g_h1[0][i];
    }
}

// ---------------- xproj GEMM: Xp_g[t*B+b][n] = emb(tok) @ Wg0[:,H:]^T + bg0 -------
__global__ void xproj_gemm(const int* __restrict__ tok, const float* __restrict__ emb,
                           const float* __restrict__ Wr0, const float* __restrict__ Wz0,
                           const float* __restrict__ Wh0,
                           const float* __restrict__ br0, const float* __restrict__ bz0,
                           const float* __restrict__ bh0) {
    __shared__ float As[16][128];
    __shared__ float Bs[16][128];
    __shared__ int stok[128];
    int n0 = blockIdx.x * 128;
    int m0 = blockIdx.y * 128;
    int g = n0 / H_;
    int nb = n0 % H_;
    const float* W = (g == 0) ? Wr0 : (g == 1) ? Wz0 : Wh0;
    const float* bias = (g == 0) ? br0 : (g == 1) ? bz0 : bh0;
    int tid = threadIdx.x;
    if (tid < 128) stok[tid] = tok[m0 + tid];
    __syncthreads();
    int tx = tid % 16, ty = tid / 16;
    float acc[8][8];
    #pragma unroll
    for (int i = 0; i < 8; i++)
        #pragma unroll
        for (int j = 0; j < 8; j++) acc[i][j] = 0.f;

    for (int k0 = 0; k0 < E_; k0 += 16) {
        #pragma unroll
        for (int r = 0; r < 2; r++) {
            int f = tid + r * 256;
            int row = f >> 2, q = f & 3;
            int t = stok[row];
            float4 v = *(const float4*)&emb[(size_t)t * E_ + k0 + q * 4];
            As[q * 4 + 0][row] = v.x; As[q * 4 + 1][row] = v.y;
            As[q * 4 + 2][row] = v.z; As[q * 4 + 3][row] = v.w;
        }
        #pragma unroll
        for (int r = 0; r < 2; r++) {
            int f = tid + r * 256;
            int row = f >> 2, q = f & 3;
            float4 v = *(const float4*)&W[(size_t)(nb + row) * (H_ + E_) + H_ + k0 + q * 4];
            Bs[q * 4 + 0][row] = v.x; Bs[q * 4 + 1][row] = v.y;
            Bs[q * 4 + 2][row] = v.z; Bs[q * 4 + 3][row] = v.w;
        }
        __syncthreads();
        #pragma unroll
        for (int kk = 0; kk < 16; kk++) {
            float a[8], bv[8];
            *(float4*)&a[0] = *(const float4*)&As[kk][ty * 8];
            *(float4*)&a[4] = *(const float4*)&As[kk][ty * 8 + 4];
            *(float4*)&bv[0] = *(const float4*)&Bs[kk][tx * 8];
            *(float4*)&bv[4] = *(const float4*)&Bs[kk][tx * 8 + 4];
            #pragma unroll
            for (int i = 0; i < 8; i++)
                #pragma unroll
                for (int j = 0; j < 8; j++) acc[i][j] = fmaf(a[i], bv[j], acc[i][j]);
        }
        __syncthreads();
    }
    float bfrag[8];
    *(float4*)&bfrag[0] = *(const float4*)&bias[nb + tx * 8];
    *(float4*)&bfrag[4] = *(const float4*)&bias[nb + tx * 8 + 4];
    float* Xg = g_Xp + (size_t)g * S_ * B_ * H_;
    #pragma unroll
    for (int i = 0; i < 8; i++) {
        int row = m0 + ty * 8 + i;           // row == t*B + b
        #pragma unroll
        for (int j = 0; j < 8; j++) {
            int n = nb + tx * 8 + j;
            Xg[(size_t)row * H_ + n] = acc[i][j] + bfrag[j];
        }
    }
}

// ---------------- recurrence role (CTAs 0..63), layer-pipelined, sync-free phases --
__device__ void recurrence_role(float* sm,
                  const float* __restrict__ Wr0, const float* __restrict__ Wz0,
                  const float* __restrict__ Wh0,
                  const float* __restrict__ Wr1, const float* __restrict__ Wz1,
                  const float* __restrict__ Wh1,
                  const float* __restrict__ br1, const float* __restrict__ bz1,
                  const float* __restrict__ bh1) {
    int tid = threadIdx.x;
    int n0 = blockIdx.x * 8;
    int cg = tid & 7;
    int b = tid >> 3;            // 0..63
    int n = n0 + cg;

    for (int j = tid; j < 3072; j += TPB) {
        int g = j >> 10, rem = j & 1023;
        int r = rem >> 7, k4 = rem & 127;
        const float* Ws = (g == 0) ? Wr0 : (g == 1) ? Wz0 : Wh0;
        *(float4*)(sm + g * W0GATE + r * W0ROW + k4 * 4) =
            *(const float4*)&Ws[(size_t)(n0 + r) * (H_ + E_) + k4 * 4];
    }
    for (int j = tid; j < 6144; j += TPB) {
        int g = j >> 11, rem = j & 2047;
        int r = rem >> 8, k4 = rem & 255;
        const float* Ws = (g == 0) ? Wr1 : (g == 1) ? Wz1 : Wh1;
        *(float4*)(sm + SM_W1 + g * W1GATE + r * W1ROW + k4 * 4) =
            *(const float4*)&Ws[(size_t)(n0 + r) * 1024 + k4 * 4];
    }
    const float* wr0p = sm + 0 * W0GATE + cg * W0ROW;
    const float* wz0p = sm + 1 * W0GATE + cg * W0ROW;
    const float* wh0p = sm + 2 * W0GATE + cg * W0ROW;
    const float* wr1p = sm + SM_W1 + 0 * W1GATE + cg * W1ROW;
    const float* wz1p = sm + SM_W1 + 1 * W1GATE + cg * W1ROW;
    const float* wh1p = sm + SM_W1 + 2 * W1GATE + cg * W1ROW;
    float vbr1 = br1[n], vbz1 = bz1[n], vbh1 = bh1[n];
    __syncthreads();             // weights CTA-local; init kernel already done

    float z0 = 0.f, h0o = 0.f, z1 = 0.f, h1o = 0.f;

    // Tick u: PhA = gates(L0 @ t=u, L1 @ t=u-1); PhB = candidates + updates
    for (int u = 0; u <= S_; ++u) {
        const float* h0c = g_h0[u & 1];           // h0(u-1)
        float* h0n = g_h0[(u & 1) ^ 1];           // h0(u) dest
        const float* h1c = g_h1[(u + 1) & 1];     // h1(u-2)
        float* h1n = g_h1[u & 1];                 // h1(u-1) dest
        size_t xo = ((size_t)u * B_ + b) * H_ + n;

        // ======== PhA ========
        {
            unsigned long long pr0[2] = {0, 0}, pz0[2] = {0, 0};
            unsigned long long pr1[2] = {0, 0}, pz1[2] = {0, 0};
            if (u > 0) dotrz(h1c + b * H_, wr1p, wz1p, pr1, pz1);
            if (u > 0 && u < S_)
                dotrz4(h0c + b * H_, wr0p, wz0p, wr1p + H_, wz1p + H_,
                       pr0, pz0, pr1, pz1);
            else if (u < S_)
                dotrz(h0c + b * H_, wr0p, wz0p, pr0, pz0);
            else
                dotrz(h0c + b * H_, wr1p + H_, wz1p + H_, pr1, pz1);
            if (u < S_) {
                float r = sigmoidf_(unpack_sum(pr0[0]) + unpack_sum(pr0[1]) + g_Xp[xo]);
                z0 = sigmoidf_(unpack_sum(pz0[0]) + unpack_sum(pz0[1])
                               + g_Xp[(size_t)S_ * B_ * H_ + xo]);
                h0o = ld_cv_f(h0c + b * H_ + n);
                g_rh0[b * H_ + n] = r * h0o;
            }
            if (u > 0) {
                float r = sigmoidf_(unpack_sum(pr1[0]) + unpack_sum(pr1[1]) + vbr1);
                z1 = sigmoidf_(unpack_sum(pz1[0]) + unpack_sum(pz1[1]) + vbz1);
                h1o = ld_cv_f(h1c + b * H_ + n);
                g_rh1[b * H_ + n] = r * h1o;
            }
        }
        grid_barrier();

        // ======== PhB ========
        if (u < S_) {
            unsigned long long p[4] = {0, 0, 0, 0};
            doth(g_rh0 + b * H_, wh0p, p);
            float ht = tanhf(unpack_sum(p[0]) + unpack_sum(p[1]) + unpack_sum(p[2])
                             + unpack_sum(p[3]) + g_Xp[2 * (size_t)S_ * B_ * H_ + xo]);
            h0n[b * H_ + n] = (1.f - z0) * h0o + z0 * ht;
        }
        if (u > 0) {
            unsigned long long p[4] = {0, 0, 0, 0};
            doth(g_rh1 + b * H_, wh1p, p);
            doth(h0c + b * H_, wh1p + H_, p);
            float ht = tanhf(unpack_sum(p[0]) + unpack_sum(p[1]) + unpack_sum(p[2])
                             + unpack_sum(p[3]) + vbh1);
            float hv = (1.f - z1) * h1o + z1 * ht;
            h1n[b * H_ + n] = hv;
            g_H1[((size_t)(u - 1) * B_ + b) * H_ + n] = hv;
        }
        grid_barrier();
        if (u > 0 && blockIdx.x == 0 && tid == 0) {
            __threadfence();
            atomicExch(&g_progress, u - 1);
        }
    }
}

// ---------------- logits role: tile-queue consumers (512 thr, row-pair f32x2) ----
__device__ void logits_role(float* sm, const float* __restrict__ Wy,
                            const float* __restrict__ by, float* __restrict__ out) {
    float* As = sm;                 // [16][128]
    float* Bs = sm + 2048;          // [16][128]
    int* s_idx = (int*)(sm + 4096);
    int tid = threadIdx.x;
    int tx = tid & 31;              // 0..31
    int ty = tid >> 5;              // 0..15
    const float* A = g_H1;

    while (true) {
        if (tid == 0) *s_idx = atomicAdd(&g_tile_ctr, 1);
        __syncthreads();
        int idx = *s_idx;
        __syncthreads();
        if (idx >= NTM * NTN) break;
        int mtile = idx / NTN, ntile = idx % NTN;
        int m0 = mtile * 128, n0 = ntile * 128;
        int need = mtile * 2 + 1;
        if (tid == 0) {
            while (*((volatile int*)&g_progress) < need) { __nanosleep(200); }
        }
        __syncthreads();
        __threadfence();

        unsigned long long acc2[4][4];
        #pragma unroll
        for (int i = 0; i < 4; i++)
            #pragma unroll
            for (int j = 0; j < 4; j++) acc2[i][j] = 0ull;

        for (int k0 = 0; k0 < H_; k0 += 16) {
            {
                int f = tid;
                int row = f >> 2, q = f & 3;
                float4 v = *(const float4*)&A[(size_t)(m0 + row) * H_ + k0 + q * 4];
                As[(q * 4 + 0) * 128 + row] = v.x; As[(q * 4 + 1) * 128 + row] = v.y;
                As[(q * 4 + 2) * 128 + row] = v.z; As[(q * 4 + 3) * 128 + row] = v.w;
                int nn = n0 + row;
                float4 w = make_float4(0.f, 0.f, 0.f, 0.f);
                if (nn < V_) w = *(const float4*)&Wy[(size_t)nn * H_ + k0 + q * 4];
                Bs[(q * 4 + 0) * 128 + row] = w.x; Bs[(q * 4 + 1) * 128 + row] = w.y;
                Bs[(q * 4 + 2) * 128 + row] = w.z; Bs[(q * 4 + 3) * 128 + row] = w.w;
            }
            __syncthreads();
            #pragma unroll
            for (int kk = 0; kk < 16; kk++) {
                ulonglong2 a01 = *(const ulonglong2*)&As[kk * 128 + ty * 4];
                ulonglong2 a23 = *(const ulonglong2*)&As[kk * 128 + 64 + ty * 4];
                float2 bA = *(const float2*)&Bs[kk * 128 + tx * 2];
                float2 bB = *(const float2*)&Bs[kk * 128 + 64 + tx * 2];
                unsigned long long d0 = dup2(bA.x), d1 = dup2(bA.y);
                unsigned long long d2 = dup2(bB.x), d3 = dup2(bB.y);
                fma2(acc2[0][0], a01.x, d0); fma2(acc2[0][1], a01.x, d1);
                fma2(acc2[0][2], a01.x, d2); fma2(acc2[0][3], a01.x, d3);
                fma2(acc2[1][0], a01.y, d0); fma2(acc2[1][1], a01.y, d1);
                fma2(acc2[1][2], a01.y, d2); fma2(acc2[1][3], a01.y, d3);
                fma2(acc2[2][0], a23.x, d0); fma2(acc2[2][1], a23.x, d1);
                fma2(acc2[2][2], a23.x, d2); fma2(acc2[2][3], a23.x, d3);
                fma2(acc2[3][0], a23.y, d0); fma2(acc2[3][1], a23.y, d1);
                fma2(acc2[3][2], a23.y, d2); fma2(acc2[3][3], a23.y, d3);
            }
            __syncthreads();
        }
        #pragma unroll
        for (int p = 0; p < 4; p++) {
            int rbase = (p < 2) ? (ty * 4 + p * 2) : (64 + ty * 4 + (p - 2) * 2);
            #pragma unroll
            for (int j = 0; j < 4; j++) {
                int col = n0 + ((j < 2) ? (tx * 2 + j) : (64 + tx * 2 + (j - 2)));
                if (col < V_) {
                    float bb = by[col];
                    float lo = __uint_as_float((unsigned)acc2[p][j]);
                    float hi = __uint_as_float((unsigned)(acc2[p][j] >> 32));
                    out[(size_t)(m0 + rbase) * V_ + col] = lo + bb;
                    out[(size_t)(m0 + rbase + 1) * V_ + col] = hi + bb;
                }
            }
        }
    }
}

// ---------------- fused kernel ----------------
__global__ void __launch_bounds__(TPB)
fused_kernel(const float* __restrict__ Wr0, const float* __restrict__ Wz0,
             const float* __restrict__ Wh0,
             const float* __restrict__ Wr1, const float* __restrict__ Wz1,
             const float* __restrict__ Wh1,
             const float* __restrict__ br1, const float* __restrict__ bz1,
             const float* __restrict__ bh1,
             const float* __restrict__ Wy, const float* __restrict__ by,
             float* __restrict__ out) {
    extern __shared__ float sm[];
    if (blockIdx.x < NB) {
        recurrence_role(sm, Wr0, Wz0, Wh0, Wr1, Wz1, Wh1, br1, bz1, bh1);
        __syncthreads();
    }
    logits_role(sm, Wy, by, out);
}

// ---------------- launch ----------------
extern "C" void kernel_launch(void* const* d_in, const int* in_sizes, int n_in,
                              void* d_out, int out_size) {
    const int*   inputs = (const int*)d_in[0];
    const float* hidden = (const float*)d_in[1];
    const float* emb    = (const float*)d_in[2];
    const float* W_r0 = (const float*)d_in[3];
    const float* b_r0 = (const float*)d_in[4];
    const float* W_z0 = (const float*)d_in[5];
    const float* b_z0 = (const float*)d_in[6];
    const float* W_h0 = (const float*)d_in[7];
    const float* b_h0 = (const float*)d_in[8];
    const float* W_r1 = (const float*)d_in[9];
    const float* b_r1 = (const float*)d_in[10];
    const float* W_z1 = (const float*)d_in[11];
    const float* b_z1 = (const float*)d_in[12];
    const float* W_h1 = (const float*)d_in[13];
    const float* b_h1 = (const float*)d_in[14];
    const float* Wy   = (const float*)d_in[15];
    const float* by   = (const float*)d_in[16];
    float* out = (float*)d_out;

    cudaFuncSetAttribute(fused_kernel, cudaFuncAttributeMaxDynamicSharedMemorySize,
                         SMEM_BYTES);

    xproj_gemm<<<dim3(3 * H_ / 128, (S_ * B_) / 128), 256>>>(inputs, emb, W_r0, W_z0, W_h0,
                                                             b_r0, b_z0, b_h0);
    init_hidden_kernel<<<(B_ * H_ + 255) / 256, 256>>>(hidden);
    fused_kernel<<<NCTA, TPB, SMEM_BYTES>>>(W_r0, W_z0, W_h0, W_r1, W_z1, W_h1,
                                            b_r1, b_z1, b_h1, Wy, by, out);

    long long logits_elems = (long long)S_ * B_ * V_;
    if ((long long)out_size >= logits_elems + 2LL * B_ * H_) {
        write_hidden_kernel<<<(B_ * H_ + 255) / 256, 256>>>(out, logits_elems);
    }
}

// round 9
// speedup vs baseline: 1.0971x; 1.0971x over previous
#include <cuda_runtime.h>
#include <math.h>

// Problem constants
#define S_ 128
#define B_ 64
#define V_ 10000
#define E_ 256
#define H_ 512

// Fused kernel config
#define NB 64            // recurrence CTAs (1/SM, co-resident)
#define NCTA 148         // total CTAs
#define TPB 512
#define KC 128
#define NTN 79           // logits n-tiles
#define NTM 64           // logits m-tiles

typedef unsigned long long ull;

// ---------------- device scratch ----------------
// State layout [k][b] (k-major), ping-pong buffers.
__device__ float g_h0[2][H_ * B_];
__device__ float g_h1[2][H_ * B_];
__device__ float g_rh0[H_ * B_];
__device__ float g_rh1[H_ * B_];
__device__ float g_Xp[3u * S_ * H_ * B_];    // [gate][t][n][b]
__device__ float g_H1[(size_t)S_ * B_ * H_]; // [t*B+b][k]
__device__ unsigned g_bar_count = 0;
__device__ unsigned g_genv[16 * 32];
__device__ int g_progress;
__device__ int g_tile_ctr;

// ---------------- packed f32x2 helpers ----------------
__device__ __forceinline__ void fma2(ull& acc, ull a, ull w) {
    asm("fma.rn.f32x2 %0, %1, %2, %0;" : "+l"(acc) : "l"(a), "l"(w));
}
__device__ __forceinline__ float up2(const ull* p) {
    return __uint_as_float((unsigned)p[0]) + __uint_as_float((unsigned)(p[0] >> 32))
         + __uint_as_float((unsigned)p[1]) + __uint_as_float((unsigned)(p[1] >> 32));
}
__device__ __forceinline__ ull dup2(float f) {
    ull d;
    asm("mov.b64 %0, {%1, %1};" : "=l"(d) : "r"(__float_as_uint(f)));
    return d;
}
__device__ __forceinline__ float sigmoidf_(float x) { return 1.0f / (1.0f + expf(-x)); }

// ---------------- grid barrier (NB recurrence CTAs only) ----------------
__device__ __forceinline__ void grid_barrier() {
    __syncthreads();
    if (threadIdx.x == 0) {
        __threadfence();
        unsigned slot = (blockIdx.x & 15) * 32;
        unsigned old = *((volatile unsigned*)&g_genv[slot]);
        unsigned t = atomicAdd(&g_bar_count, 1u);
        if (t == NB - 1) {
            g_bar_count = 0;
            __threadfence();
            #pragma unroll
            for (int i = 0; i < 16; i++)
                *((volatile unsigned*)&g_genv[i * 32]) = old + 1;
        } else {
            while (*((volatile unsigned*)&g_genv[slot]) == old) { }
        }
        __threadfence();
    }
    __syncthreads();
}

// ---------------- recurrence smem layout ----------------
#define W0ROW 516
#define W1ROW 1028
#define W0GATE (8 * W0ROW)
#define W1GATE (8 * W1ROW)
#define SM_W1 (3 * W0GATE)                   // 12384
#define SM_SA (SM_W1 + 3 * W1GATE)           // 37056
#define SAROW 132
#define SABUF (B_ * SAROW)                   // 8448
#define SM_FLOATS (SM_SA + 2 * SABUF)        // 53952
#define SMEM_BYTES (SM_FLOATS * 4)           // 215808

// ---------------- staging: global [k][b] -> regs (.cg) -> smem [b][k] ------------
__device__ __forceinline__ void gather16(float* rg, const float* __restrict__ src) {
    int sb = threadIdx.x & 63;
    int kq = threadIdx.x >> 6;               // 0..7, 16 k each
    const float* s = src + kq * 16 * B_ + sb;
    #pragma unroll
    for (int i = 0; i < 16; i++) rg[i] = __ldcg(s + i * B_);
}
__device__ __forceinline__ void sts16(float* buf, const float* rg) {
    int sb = threadIdx.x & 63;
    int kq = threadIdx.x >> 6;
    float* d = buf + sb * SAROW + kq * 16;
    #pragma unroll
    for (int i = 0; i < 16; i += 4)
        *(float4*)(d + i) = make_float4(rg[i], rg[i + 1], rg[i + 2], rg[i + 3]);
}

// ---------------- fused chunk dot products (per-thread: 1 b, 1 n) ----------------
// 5-gate fused dot over an h0c chunk: Wr0, Wz0, Wr1hi, Wz1hi, Wh1hi.
__device__ __forceinline__ void dot5(const float* __restrict__ a,
                                     const float* __restrict__ w0r,
                                     const float* __restrict__ w0z,
                                     const float* __restrict__ w1r,
                                     const float* __restrict__ w1z,
                                     const float* __restrict__ w1h,
                                     ull* pr0, ull* pz0, ull* pr1, ull* pz1, ull* ph1) {
    #pragma unroll
    for (int kk = 0; kk < KC; kk += 4) {
        ulonglong2 x = *(const ulonglong2*)(a + kk);
        ulonglong2 wa = *(const ulonglong2*)(w0r + kk);
        ulonglong2 wb = *(const ulonglong2*)(w0z + kk);
        ulonglong2 wc = *(const ulonglong2*)(w1r + kk);
        ulonglong2 wd = *(const ulonglong2*)(w1z + kk);
        ulonglong2 we = *(const ulonglong2*)(w1h + kk);
        fma2(pr0[0], x.x, wa.x); fma2(pr0[1], x.y, wa.y);
        fma2(pz0[0], x.x, wb.x); fma2(pz0[1], x.y, wb.y);
        fma2(pr1[0], x.x, wc.x); fma2(pr1[1], x.y, wc.y);
        fma2(pz1[0], x.x, wd.x); fma2(pz1[1], x.y, wd.y);
        fma2(ph1[0], x.x, we.x); fma2(ph1[1], x.y, we.y);
    }
}
__device__ __forceinline__ void dot2(const float* __restrict__ a,
                                     const float* __restrict__ wr,
                                     const float* __restrict__ wz,
                                     ull* pr, ull* pz) {
    #pragma unroll
    for (int kk = 0; kk < KC; kk += 4) {
        ulonglong2 x = *(const ulonglong2*)(a + kk);
        ulonglong2 w1 = *(const ulonglong2*)(wr + kk);
        ulonglong2 w2 = *(const ulonglong2*)(wz + kk);
        fma2(pr[0], x.x, w1.x); fma2(pr[1], x.y, w1.y);
        fma2(pz[0], x.x, w2.x); fma2(pz[1], x.y, w2.y);
    }
}
__device__ __forceinline__ void dot1(const float* __restrict__ a,
                                     const float* __restrict__ w, ull* p) {
    #pragma unroll
    for (int kk = 0; kk < KC; kk += 4) {
        ulonglong2 x = *(const ulonglong2*)(a + kk);
        ulonglong2 wv = *(const ulonglong2*)(w + kk);
        fma2(p[0], x.x, wv.x); fma2(p[1], x.y, wv.y);
    }
}

// ---------------- init / finalize ----------------
__global__ void init_hidden_kernel(const float* __restrict__ hidden) {
    int i = blockIdx.x * blockDim.x + threadIdx.x;
    if (i < B_ * H_) {
        int b = i / H_, k = i % H_;
        g_h0[0][k * B_ + b] = hidden[i];
        g_h1[0][k * B_ + b] = hidden[B_ * H_ + i];
    }
    if (blockIdx.x == 0 && threadIdx.x == 0) {
        g_progress = -1;
        g_tile_ctr = 0;
    }
}
__global__ void write_hidden_kernel(float* __restrict__ out, long long off) {
    int i = blockIdx.x * blockDim.x + threadIdx.x;
    if (i < B_ * H_) {
        int b = i / H_, k = i % H_;
        out[off + i] = g_h0[0][k * B_ + b];            // finals land in buf 0
        out[off + B_ * H_ + i] = g_h1[0][k * B_ + b];
    }
}

// ---------------- xproj GEMM: Xp_g[t][n][b] = emb(tok) @ Wg0[:,H:]^T + bg0 -------
__global__ void xproj_gemm(const int* __restrict__ tok, const float* __restrict__ emb,
                           const float* __restrict__ Wr0, const float* __restrict__ Wz0,
                           const float* __restrict__ Wh0,
                           const float* __restrict__ br0, const float* __restrict__ bz0,
                           const float* __restrict__ bh0) {
    __shared__ float As[16][128];
    __shared__ float Bs[16][128];
    __shared__ int stok[128];
    int n0 = blockIdx.x * 128;
    int m0 = blockIdx.y * 128;
    int g = n0 / H_;
    int nb = n0 % H_;
    const float* W = (g == 0) ? Wr0 : (g == 1) ? Wz0 : Wh0;
    const float* bias = (g == 0) ? br0 : (g == 1) ? bz0 : bh0;
    int tid = threadIdx.x;
    if (tid < 128) stok[tid] = tok[m0 + tid];
    __syncthreads();
    int tx = tid % 16, ty = tid / 16;
    float acc[8][8];
    #pragma unroll
    for (int i = 0; i < 8; i++)
        #pragma unroll
        for (int j = 0; j < 8; j++) acc[i][j] = 0.f;

    for (int k0 = 0; k0 < E_; k0 += 16) {
        #pragma unroll
        for (int r = 0; r < 2; r++) {
            int f = tid + r * 256;
            int row = f >> 2, q = f & 3;
            int t = stok[row];
            float4 v = *(const float4*)&emb[(size_t)t * E_ + k0 + q * 4];
            As[q * 4 + 0][row] = v.x; As[q * 4 + 1][row] = v.y;
            As[q * 4 + 2][row] = v.z; As[q * 4 + 3][row] = v.w;
        }
        #pragma unroll
        for (int r = 0; r < 2; r++) {
            int f = tid + r * 256;
            int row = f >> 2, q = f & 3;
            float4 v = *(const float4*)&W[(size_t)(nb + row) * (H_ + E_) + H_ + k0 + q * 4];
            Bs[q * 4 + 0][row] = v.x; Bs[q * 4 + 1][row] = v.y;
            Bs[q * 4 + 2][row] = v.z; Bs[q * 4 + 3][row] = v.w;
        }
        __syncthreads();
        #pragma unroll
        for (int kk = 0; kk < 16; kk++) {
            float a[8], bv[8];
            *(float4*)&a[0] = *(const float4*)&As[kk][ty * 8];
            *(float4*)&a[4] = *(const float4*)&As[kk][ty * 8 + 4];
            *(float4*)&bv[0] = *(const float4*)&Bs[kk][tx * 8];
            *(float4*)&bv[4] = *(const float4*)&Bs[kk][tx * 8 + 4];
            #pragma unroll
            for (int i = 0; i < 8; i++)
                #pragma unroll
                for (int j = 0; j < 8; j++) acc[i][j] = fmaf(a[i], bv[j], acc[i][j]);
        }
        __syncthreads();
    }
    float bfrag[8];
    *(float4*)&bfrag[0] = *(const float4*)&bias[nb + tx * 8];
    *(float4*)&bfrag[4] = *(const float4*)&bias[nb + tx * 8 + 4];
    float* Xg = g_Xp + (size_t)g * S_ * H_ * B_;
    #pragma unroll
    for (int i = 0; i < 8; i++) {
        int row = m0 + ty * 8 + i;
        int t = row >> 6, b = row & 63;
        #pragma unroll
        for (int j = 0; j < 8; j++) {
            int n = nb + tx * 8 + j;
            Xg[((size_t)t * H_ + n) * B_ + b] = acc[i][j] + bfrag[j];
        }
    }
}

// ---------------- recurrence role (CTAs 0..63): 512 thr, fused gate streams ------
__device__ void recurrence_role(float* sm,
                  const float* __restrict__ Wr0, const float* __restrict__ Wz0,
                  const float* __restrict__ Wh0,
                  const float* __restrict__ Wr1, const float* __restrict__ Wz1,
                  const float* __restrict__ Wh1,
                  const float* __restrict__ br1, const float* __restrict__ bz1,
                  const float* __restrict__ bh1) {
    int tid = threadIdx.x;
    int n0 = blockIdx.x * 8;
    int cg = tid & 7;
    int b = tid >> 3;            // 0..63 (one batch row per thread)
    int n = n0 + cg;

    // -------- preload weights --------
    for (int j = tid; j < 3072; j += TPB) {               // L0 h-part: 3x8x128 float4
        int g = j >> 10, rem = j & 1023;
        int r = rem >> 7, k4 = rem & 127;
        const float* Ws = (g == 0) ? Wr0 : (g == 1) ? Wz0 : Wh0;
        *(float4*)(sm + g * W0GATE + r * W0ROW + k4 * 4) =
            *(const float4*)&Ws[(size_t)(n0 + r) * (H_ + E_) + k4 * 4];
    }
    for (int j = tid; j < 6144; j += TPB) {               // L1: 3x8x256 float4
        int g = j >> 11, rem = j & 2047;
        int r = rem >> 8, k4 = rem & 255;
        const float* Ws = (g == 0) ? Wr1 : (g == 1) ? Wz1 : Wh1;
        *(float4*)(sm + SM_W1 + g * W1GATE + r * W1ROW + k4 * 4) =
            *(const float4*)&Ws[(size_t)(n0 + r) * 1024 + k4 * 4];
    }
    const float* wr0p = sm + 0 * W0GATE + cg * W0ROW;
    const float* wz0p = sm + 1 * W0GATE + cg * W0ROW;
    const float* wh0p = sm + 2 * W0GATE + cg * W0ROW;
    const float* wr1p = sm + SM_W1 + 0 * W1GATE + cg * W1ROW;
    const float* wz1p = sm + SM_W1 + 1 * W1GATE + cg * W1ROW;
    const float* wh1p = sm + SM_W1 + 2 * W1GATE + cg * W1ROW;
    float vbr1 = br1[n], vbz1 = bz1[n], vbh1 = bh1[n];
    float* sA = sm + SM_SA;
    const float* aRow0 = sA + b * SAROW;
    const float* aRow1 = sA + SABUF + b * SAROW;
    __syncthreads();

    float rg[16];
    float z0 = 0.f, h0o = 0.f, z1 = 0.f, h1o = 0.f;

    // Tick u: PhA = gates(L0 @ t=u; L1 @ t=u-1) + Wh1hi*h0c partial
    //         PhB = candidates + state updates
    for (int u = 0; u <= S_; ++u) {
        const float* h0c = g_h0[u & 1];           // h0(u-1)
        float* h0n = g_h0[(u & 1) ^ 1];           // h0(u) dest
        const float* h1c = g_h1[(u + 1) & 1];     // h1(u-2)
        float* h1n = g_h1[u & 1];                 // h1(u-1) dest
        size_t xo = ((size_t)u * H_ + n) * B_ + b;

        ull pr0[2] = {0, 0}, pz0[2] = {0, 0};
        ull pr1[2] = {0, 0}, pz1[2] = {0, 0};
        ull ph1[2] = {0, 0};                      // carried into PhB

        // ======== PhA: streams h0c(4 chunks, 5-gate) then h1c(4 chunks, 2-gate) ===
        gather16(rg, h0c);
        sts16(sA, rg);
        __syncthreads();
        #pragma unroll
        for (int c = 0; c < 8; c++) {
            if (c < 7) {
                const float* nsrc = (c + 1 < 4) ? (h0c + (c + 1) * KC * B_)
                                                : (h1c + (c + 1 - 4) * KC * B_);
                gather16(rg, nsrc);
            }
            const float* a = (c & 1) ? aRow1 : aRow0;
            if (c < 4) {
                int ko = c * KC;
                dot5(a, wr0p + ko, wz0p + ko, wr1p + H_ + ko, wz1p + H_ + ko,
                     wh1p + H_ + ko, pr0, pz0, pr1, pz1, ph1);
            } else {
                int ko = (c - 4) * KC;
                dot2(a, wr1p + ko, wz1p + ko, pr1, pz1);
            }
            if (c < 7) sts16(sA + ((c + 1) & 1) * SABUF, rg);
            __syncthreads();
        }
        if (u < S_) {
            float r0 = sigmoidf_(up2(pr0) + g_Xp[xo]);
            z0 = sigmoidf_(up2(pz0) + g_Xp[(size_t)S_ * H_ * B_ + xo]);
            h0o = __ldcg(h0c + n * B_ + b);
            g_rh0[n * B_ + b] = r0 * h0o;
        }
        if (u > 0) {
            float r1 = sigmoidf_(up2(pr1) + vbr1);
            z1 = sigmoidf_(up2(pz1) + vbz1);
            h1o = __ldcg(h1c + n * B_ + b);
            g_rh1[n * B_ + b] = r1 * h1o;
        }
        grid_barrier();

        // ======== PhB: streams rh0(4 chunks) then rh1(4 chunks) ========
        ull ph0[2] = {0, 0};
        gather16(rg, g_rh0);
        sts16(sA, rg);
        __syncthreads();
        #pragma unroll
        for (int c = 0; c < 8; c++) {
            if (c < 7) {
                const float* nsrc = (c + 1 < 4) ? (g_rh0 + (c + 1) * KC * B_)
                                                : (g_rh1 + (c + 1 - 4) * KC * B_);
                gather16(rg, nsrc);
            }
            const float* a = (c & 1) ? aRow1 : aRow0;
            if (c < 4) dot1(a, wh0p + c * KC, ph0);
            else       dot1(a, wh1p + (c - 4) * KC, ph1);
            if (c < 7) sts16(sA + ((c + 1) & 1) * SABUF, rg);
            __syncthreads();
        }
        if (u < S_) {
            float ht = tanhf(up2(ph0) + g_Xp[2 * (size_t)S_ * H_ * B_ + xo]);
            h0n[n * B_ + b] = (1.f - z0) * h0o + z0 * ht;
        }
        if (u > 0) {
            float ht = tanhf(up2(ph1) + vbh1);
            float hv = (1.f - z1) * h1o + z1 * ht;
            h1n[n * B_ + b] = hv;
            g_H1[((size_t)(u - 1) * B_ + b) * H_ + n] = hv;
        }
        grid_barrier();
        if (u > 0 && blockIdx.x == 0 && tid == 0) {
            __threadfence();
            atomicExch(&g_progress, u - 1);
        }
    }
}

// ---------------- logits role: tile-queue consumers (512 thr) ----------------
__device__ void logits_role(float* sm, const float* __restrict__ Wy,
                            const float* __restrict__ by, float* __restrict__ out) {
    float* As = sm;                 // [16][128]
    float* Bs = sm + 2048;          // [16][128]
    int* s_idx = (int*)(sm + 4096);
    int tid = threadIdx.x;
    int tx = tid & 31;              // 0..31
    int ty = tid >> 5;              // 0..15
    const float* A = g_H1;

    while (true) {
        if (tid == 0) *s_idx = atomicAdd(&g_tile_ctr, 1);
        __syncthreads();
        int idx = *s_idx;
        __syncthreads();
        if (idx >= NTM * NTN) break;
        int mtile = idx / NTN, ntile = idx % NTN;
        int m0 = mtile * 128, n0 = ntile * 128;
        int need = mtile * 2 + 1;
        if (tid == 0) {
            while (*((volatile int*)&g_progress) < need) { __nanosleep(200); }
        }
        __syncthreads();
        __threadfence();

        ull acc2[4][4];
        #pragma unroll
        for (int i = 0; i < 4; i++)
            #pragma unroll
            for (int j = 0; j < 4; j++) acc2[i][j] = 0ull;

        for (int k0 = 0; k0 < H_; k0 += 16) {
            {
                int row = tid >> 2, q = tid & 3;
                float4 v = *(const float4*)&A[(size_t)(m0 + row) * H_ + k0 + q * 4];
                As[(q * 4 + 0) * 128 + row] = v.x; As[(q * 4 + 1) * 128 + row] = v.y;
                As[(q * 4 + 2) * 128 + row] = v.z; As[(q * 4 + 3) * 128 + row] = v.w;
                int nn = n0 + row;
                float4 w = make_float4(0.f, 0.f, 0.f, 0.f);
                if (nn < V_) w = *(const float4*)&Wy[(size_t)nn * H_ + k0 + q * 4];
                Bs[(q * 4 + 0) * 128 + row] = w.x; Bs[(q * 4 + 1) * 128 + row] = w.y;
                Bs[(q * 4 + 2) * 128 + row] = w.z; Bs[(q * 4 + 3) * 128 + row] = w.w;
            }
            __syncthreads();
            #pragma unroll
            for (int kk = 0; kk < 16; kk++) {
                ulonglong2 a01 = *(const ulonglong2*)&As[kk * 128 + ty * 4];
                ulonglong2 a23 = *(const ulonglong2*)&As[kk * 128 + 64 + ty * 4];
                float2 bA = *(const float2*)&Bs[kk * 128 + tx * 2];
                float2 bB = *(const float2*)&Bs[kk * 128 + 64 + tx * 2];
                ull d0 = dup2(bA.x), d1 = dup2(bA.y);
                ull d2 = dup2(bB.x), d3 = dup2(bB.y);
                fma2(acc2[0][0], a01.x, d0); fma2(acc2[0][1], a01.x, d1);
                fma2(acc2[0][2], a01.x, d2); fma2(acc2[0][3], a01.x, d3);
                fma2(acc2[1][0], a01.y, d0); fma2(acc2[1][1], a01.y, d1);
                fma2(acc2[1][2], a01.y, d2); fma2(acc2[1][3], a01.y, d3);
                fma2(acc2[2][0], a23.x, d0); fma2(acc2[2][1], a23.x, d1);
                fma2(acc2[2][2], a23.x, d2); fma2(acc2[2][3], a23.x, d3);
                fma2(acc2[3][0], a23.y, d0); fma2(acc2[3][1], a23.y, d1);
                fma2(acc2[3][2], a23.y, d2); fma2(acc2[3][3], a23.y, d3);
            }
            __syncthreads();
        }
        #pragma unroll
        for (int p = 0; p < 4; p++) {
            int rbase = (p < 2) ? (ty * 4 + p * 2) : (64 + ty * 4 + (p - 2) * 2);
            #pragma unroll
            for (int j = 0; j < 4; j++) {
                int col = n0 + ((j < 2) ? (tx * 2 + j) : (64 + tx * 2 + (j - 2)));
                if (col < V_) {
                    float bb = by[col];
                    float lo = __uint_as_float((unsigned)acc2[p][j]);
                    float hi = __uint_as_float((unsigned)(acc2[p][j] >> 32));
                    out[(size_t)(m0 + rbase) * V_ + col] = lo + bb;
                    out[(size_t)(m0 + rbase + 1) * V_ + col] = hi + bb;
                }
            }
        }
    }
}

// ---------------- fused kernel ----------------
__global__ void __launch_bounds__(TPB)
fused_kernel(const float* __restrict__ Wr0, const float* __restrict__ Wz0,
             const float* __restrict__ Wh0,
             const float* __restrict__ Wr1, const float* __restrict__ Wz1,
             const float* __restrict__ Wh1,
             const float* __restrict__ br1, const float* __restrict__ bz1,
             const float* __restrict__ bh1,
             const float* __restrict__ Wy, const float* __restrict__ by,
             float* __restrict__ out) {
    extern __shared__ float sm[];
    if (blockIdx.x < NB) {
        recurrence_role(sm, Wr0, Wz0, Wh0, Wr1, Wz1, Wh1, br1, bz1, bh1);
        __syncthreads();
    }
    logits_role(sm, Wy, by, out);
}

// ---------------- launch ----------------
extern "C" void kernel_launch(void* const* d_in, const int* in_sizes, int n_in,
                              void* d_out, int out_size) {
    const int*   inputs = (const int*)d_in[0];
    const float* hidden = (const float*)d_in[1];
    const float* emb    = (const float*)d_in[2];
    const float* W_r0 = (const float*)d_in[3];
    const float* b_r0 = (const float*)d_in[4];
    const float* W_z0 = (const float*)d_in[5];
    const float* b_z0 = (const float*)d_in[6];
    const float* W_h0 = (const float*)d_in[7];
    const float* b_h0 = (const float*)d_in[8];
    const float* W_r1 = (const float*)d_in[9];
    const float* b_r1 = (const float*)d_in[10];
    const float* W_z1 = (const float*)d_in[11];
    const float* b_z1 = (const float*)d_in[12];
    const float* W_h1 = (const float*)d_in[13];
    const float* b_h1 = (const float*)d_in[14];
    const float* Wy   = (const float*)d_in[15];
    const float* by   = (const float*)d_in[16];
    float* out = (float*)d_out;

    cudaFuncSetAttribute(fused_kernel, cudaFuncAttributeMaxDynamicSharedMemorySize,
                         SMEM_BYTES);

    xproj_gemm<<<dim3(3 * H_ / 128, (S_ * B_) / 128), 256>>>(inputs, emb, W_r0, W_z0, W_h0,
                                                             b_r0, b_z0, b_h0);
    init_hidden_kernel<<<(B_ * H_ + 255) / 256, 256>>>(hidden);
    fused_kernel<<<NCTA, TPB, SMEM_BYTES>>>(W_r0, W_z0, W_h0, W_r1, W_z1, W_h1,
                                            b_r1, b_z1, b_h1, Wy, by, out);

    long long logits_elems = (long long)S_ * B_ * V_;
    if ((long long)out_size >= logits_elems + 2LL * B_ * H_) {
        write_hidden_kernel<<<(B_ * H_ + 255) / 256, 256>>>(out, logits_elems);
    }
}

// round 10
// speedup vs baseline: 1.5267x; 1.3916x over previous
#include <cuda_runtime.h>
#include <math.h>

// Problem constants
#define S_ 128
#define B_ 64
#define V_ 10000
#define E_ 256
#define H_ 512

// Fused kernel config
#define NB 64            // recurrence CTAs (1/SM, co-resident)
#define NCTA 148         // total CTAs
#define TPB 256
#define KC 128
#define NTN 79           // logits n-tiles
#define NTM 64           // logits m-tiles

typedef unsigned long long ull;

// ---------------- device scratch ----------------
// State layout [k][b] (k-major), ping-pong buffers.
__device__ float g_h0[2][H_ * B_];
__device__ float g_h1[2][H_ * B_];
__device__ float g_rh0[H_ * B_];
__device__ float g_rh1[H_ * B_];
__device__ float g_Xp[3u * S_ * H_ * B_];    // [gate][t][n][b]
__device__ float g_H1[(size_t)S_ * B_ * H_]; // [t*B+b][k]
__device__ unsigned g_bar_count = 0;
__device__ unsigned g_genv[16 * 32];
__device__ int g_progress;
__device__ int g_tile_ctr;

// ---------------- packed f32x2 helpers ----------------
__device__ __forceinline__ void fma2(ull& acc, ull a, ull w) {
    asm("fma.rn.f32x2 %0, %1, %2, %0;" : "+l"(acc) : "l"(a), "l"(w));
}
__device__ __forceinline__ float upk(ull v) {
    return __uint_as_float((unsigned)v) + __uint_as_float((unsigned)(v >> 32));
}
__device__ __forceinline__ ull dup2(float f) {
    ull d;
    asm("mov.b64 %0, {%1, %1};" : "=l"(d) : "r"(__float_as_uint(f)));
    return d;
}
__device__ __forceinline__ float sigmoidf_(float x) { return 1.0f / (1.0f + expf(-x)); }

// ---------------- grid barrier (NB recurrence CTAs only) ----------------
__device__ __forceinline__ void grid_barrier() {
    __syncthreads();
    if (threadIdx.x == 0) {
        __threadfence();
        unsigned slot = (blockIdx.x & 15) * 32;
        unsigned old = *((volatile unsigned*)&g_genv[slot]);
        unsigned t = atomicAdd(&g_bar_count, 1u);
        if (t == NB - 1) {
            g_bar_count = 0;
            __threadfence();
            #pragma unroll
            for (int i = 0; i < 16; i++)
                *((volatile unsigned*)&g_genv[i * 32]) = old + 1;
        } else {
            while (*((volatile unsigned*)&g_genv[slot]) == old) { }
        }
        __threadfence();
    }
    __syncthreads();
}

// ---------------- recurrence smem layout ----------------
#define W0ROW 516
#define W1ROW 1028
#define W0GATE (8 * W0ROW)
#define W1GATE (8 * W1ROW)
#define SM_W1 (3 * W0GATE)                   // 12384
#define SM_SA (SM_W1 + 3 * W1GATE)           // 37056
#define SAROW 132
#define SABUF (B_ * SAROW)                   // 8448
#define SM_FLOATS (SM_SA + 2 * SABUF)        // 53952
#define SMEM_BYTES (SM_FLOATS * 4)           // 215808

// ---------------- staging: global [k][b] -> regs -> smem [b][k] ----------------
__device__ __forceinline__ void gather32(float* rg, const float* __restrict__ src) {
    int sb = threadIdx.x & 63;
    int kq = threadIdx.x >> 6;               // 0..3, 32 k each
    const float* s = src + kq * 32 * B_ + sb;
    #pragma unroll
    for (int i = 0; i < 32; i++) rg[i] = __ldcg(s + i * B_);
}
__device__ __forceinline__ void sts32(float* buf, const float* rg) {
    int sb = threadIdx.x & 63;
    int kq = threadIdx.x >> 6;
    float* d = buf + sb * SAROW + kq * 32;
    #pragma unroll
    for (int i = 0; i < 32; i += 4)
        *(float4*)(d + i) = make_float4(rg[i], rg[i + 1], rg[i + 2], rg[i + 3]);
}

// ---------------- fused chunk dot products (2 b-rows per thread) ----------------
// 5-gate fused: Wr0, Wz0, Wr1hi, Wz1hi, Wh1hi over one h0c chunk.
__device__ __forceinline__ void dot5_2r(const float* __restrict__ a0,
                                        const float* __restrict__ a1,
                                        const float* __restrict__ w0r,
                                        const float* __restrict__ w0z,
                                        const float* __restrict__ w1r,
                                        const float* __restrict__ w1z,
                                        const float* __restrict__ w1h,
                                        ull* pr0, ull* pz0,
                                        ull* pr1, ull* pz1, ull* ph1) {
    #pragma unroll 8
    for (int kk = 0; kk < KC; kk += 4) {
        ulonglong2 x0 = *(const ulonglong2*)(a0 + kk);
        ulonglong2 x1 = *(const ulonglong2*)(a1 + kk);
        ulonglong2 wa = *(const ulonglong2*)(w0r + kk);
        ulonglong2 wb = *(const ulonglong2*)(w0z + kk);
        ulonglong2 wc = *(const ulonglong2*)(w1r + kk);
        ulonglong2 wd = *(const ulonglong2*)(w1z + kk);
        ulonglong2 we = *(const ulonglong2*)(w1h + kk);
        fma2(pr0[0], x0.x, wa.x); fma2(pr0[1], x0.y, wa.y);
        fma2(pr0[2], x1.x, wa.x); fma2(pr0[3], x1.y, wa.y);
        fma2(pz0[0], x0.x, wb.x); fma2(pz0[1], x0.y, wb.y);
        fma2(pz0[2], x1.x, wb.x); fma2(pz0[3], x1.y, wb.y);
        fma2(pr1[0], x0.x, wc.x); fma2(pr1[1], x0.y, wc.y);
        fma2(pr1[2], x1.x, wc.x); fma2(pr1[3], x1.y, wc.y);
        fma2(pz1[0], x0.x, wd.x); fma2(pz1[1], x0.y, wd.y);
        fma2(pz1[2], x1.x, wd.x); fma2(pz1[3], x1.y, wd.y);
        fma2(ph1[0], x0.x, we.x); fma2(ph1[1], x0.y, we.y);
        fma2(ph1[2], x1.x, we.x); fma2(ph1[3], x1.y, we.y);
    }
}
__device__ __forceinline__ void dot2_2r(const float* __restrict__ a0,
                                        const float* __restrict__ a1,
                                        const float* __restrict__ wr,
                                        const float* __restrict__ wz,
                                        ull* pr, ull* pz) {
    #pragma unroll 8
    for (int kk = 0; kk < KC; kk += 4) {
        ulonglong2 x0 = *(const ulonglong2*)(a0 + kk);
        ulonglong2 x1 = *(const ulonglong2*)(a1 + kk);
        ulonglong2 w1 = *(const ulonglong2*)(wr + kk);
        ulonglong2 w2 = *(const ulonglong2*)(wz + kk);
        fma2(pr[0], x0.x, w1.x); fma2(pr[1], x0.y, w1.y);
        fma2(pr[2], x1.x, w1.x); fma2(pr[3], x1.y, w1.y);
        fma2(pz[0], x0.x, w2.x); fma2(pz[1], x0.y, w2.y);
        fma2(pz[2], x1.x, w2.x); fma2(pz[3], x1.y, w2.y);
    }
}
__device__ __forceinline__ void dot1_2r(const float* __restrict__ a0,
                                        const float* __restrict__ a1,
                                        const float* __restrict__ w, ull* p) {
    #pragma unroll 8
    for (int kk = 0; kk < KC; kk += 4) {
        ulonglong2 x0 = *(const ulonglong2*)(a0 + kk);
        ulonglong2 x1 = *(const ulonglong2*)(a1 + kk);
        ulonglong2 wv = *(const ulonglong2*)(w + kk);
        fma2(p[0], x0.x, wv.x); fma2(p[1], x0.y, wv.y);
        fma2(p[2], x1.x, wv.x); fma2(p[3], x1.y, wv.y);
    }
}

// ---------------- init / finalize ----------------
__global__ void init_hidden_kernel(const float* __restrict__ hidden) {
    int i = blockIdx.x * blockDim.x + threadIdx.x;
    if (i < B_ * H_) {
        int b = i / H_, k = i % H_;
        g_h0[0][k * B_ + b] = hidden[i];
        g_h1[0][k * B_ + b] = hidden[B_ * H_ + i];
    }
    if (blockIdx.x == 0 && threadIdx.x == 0) {
        g_progress = -1;
        g_tile_ctr = 0;
    }
}
__global__ void write_hidden_kernel(float* __restrict__ out, long long off) {
    int i = blockIdx.x * blockDim.x + threadIdx.x;
    if (i < B_ * H_) {
        int b = i / H_, k = i % H_;
        out[off + i] = g_h0[0][k * B_ + b];            // finals land in buf 0
        out[off + B_ * H_ + i] = g_h1[0][k * B_ + b];
    }
}

// ---------------- xproj GEMM: Xp_g[t][n][b] = emb(tok) @ Wg0[:,H:]^T + bg0 -------
__global__ void xproj_gemm(const int* __restrict__ tok, const float* __restrict__ emb,
                           const float* __restrict__ Wr0, const float* __restrict__ Wz0,
                           const float* __restrict__ Wh0,
                           const float* __restrict__ br0, const float* __restrict__ bz0,
                           const float* __restrict__ bh0) {
    __shared__ float As[16][128];
    __shared__ float Bs[16][128];
    __shared__ int stok[128];
    int n0 = blockIdx.x * 128;
    int m0 = blockIdx.y * 128;
    int g = n0 / H_;
    int nb = n0 % H_;
    const float* W = (g == 0) ? Wr0 : (g == 1) ? Wz0 : Wh0;
    const float* bias = (g == 0) ? br0 : (g == 1) ? bz0 : bh0;
    int tid = threadIdx.x;
    if (tid < 128) stok[tid] = tok[m0 + tid];
    __syncthreads();
    int tx = tid % 16, ty = tid / 16;
    float acc[8][8];
    #pragma unroll
    for (int i = 0; i < 8; i++)
        #pragma unroll
        for (int j = 0; j < 8; j++) acc[i][j] = 0.f;

    for (int k0 = 0; k0 < E_; k0 += 16) {
        #pragma unroll
        for (int r = 0; r < 2; r++) {
            int f = tid + r * 256;
            int row = f >> 2, q = f & 3;
            int t = stok[row];
            float4 v = *(const float4*)&emb[(size_t)t * E_ + k0 + q * 4];
            As[q * 4 + 0][row] = v.x; As[q * 4 + 1][row] = v.y;
            As[q * 4 + 2][row] = v.z; As[q * 4 + 3][row] = v.w;
        }
        #pragma unroll
        for (int r = 0; r < 2; r++) {
            int f = tid + r * 256;
            int row = f >> 2, q = f & 3;
            float4 v = *(const float4*)&W[(size_t)(nb + row) * (H_ + E_) + H_ + k0 + q * 4];
            Bs[q * 4 + 0][row] = v.x; Bs[q * 4 + 1][row] = v.y;
            Bs[q * 4 + 2][row] = v.z; Bs[q * 4 + 3][row] = v.w;
        }
        __syncthreads();
        #pragma unroll
        for (int kk = 0; kk < 16; kk++) {
            float a[8], bv[8];
            *(float4*)&a[0] = *(const float4*)&As[kk][ty * 8];
            *(float4*)&a[4] = *(const float4*)&As[kk][ty * 8 + 4];
            *(float4*)&bv[0] = *(const float4*)&Bs[kk][tx * 8];
            *(float4*)&bv[4] = *(const float4*)&Bs[kk][tx * 8 + 4];
            #pragma unroll
            for (int i = 0; i < 8; i++)
                #pragma unroll
                for (int j = 0; j < 8; j++) acc[i][j] = fmaf(a[i], bv[j], acc[i][j]);
        }
        __syncthreads();
    }
    float bfrag[8];
    *(float4*)&bfrag[0] = *(const float4*)&bias[nb + tx * 8];
    *(float4*)&bfrag[4] = *(const float4*)&bias[nb + tx * 8 + 4];
    float* Xg = g_Xp + (size_t)g * S_ * H_ * B_;
    #pragma unroll
    for (int i = 0; i < 8; i++) {
        int row = m0 + ty * 8 + i;
        int t = row >> 6, b = row & 63;
        #pragma unroll
        for (int j = 0; j < 8; j++) {
            int n = nb + tx * 8 + j;
            Xg[((size_t)t * H_ + n) * B_ + b] = acc[i][j] + bfrag[j];
        }
    }
}

// ---------------- recurrence role (CTAs 0..63): 256 thr, 2 rows, fused gates -----
__device__ void recurrence_role(float* sm,
                  const float* __restrict__ Wr0, const float* __restrict__ Wz0,
                  const float* __restrict__ Wh0,
                  const float* __restrict__ Wr1, const float* __restrict__ Wz1,
                  const float* __restrict__ Wh1,
                  const float* __restrict__ br1, const float* __restrict__ bz1,
                  const float* __restrict__ bh1) {
    int tid = threadIdx.x;
    int n0 = blockIdx.x * 8;
    int cg = tid & 7;
    int bp = tid >> 3;           // 0..31
    int b0 = bp * 2, b1 = b0 + 1;
    int n = n0 + cg;

    // -------- preload weights --------
    for (int j = tid; j < 3072; j += TPB) {               // L0 h-part: 3x8x128 float4
        int g = j >> 10, rem = j & 1023;
        int r = rem >> 7, k4 = rem & 127;
        const float* Ws = (g == 0) ? Wr0 : (g == 1) ? Wz0 : Wh0;
        *(float4*)(sm + g * W0GATE + r * W0ROW + k4 * 4) =
            *(const float4*)&Ws[(size_t)(n0 + r) * (H_ + E_) + k4 * 4];
    }
    for (int j = tid; j < 6144; j += TPB) {               // L1: 3x8x256 float4
        int g = j >> 11, rem = j & 2047;
        int r = rem >> 8, k4 = rem & 255;
        const float* Ws = (g == 0) ? Wr1 : (g == 1) ? Wz1 : Wh1;
        *(float4*)(sm + SM_W1 + g * W1GATE + r * W1ROW + k4 * 4) =
            *(const float4*)&Ws[(size_t)(n0 + r) * 1024 + k4 * 4];
    }
    const float* wr0p = sm + 0 * W0GATE + cg * W0ROW;
    const float* wz0p = sm + 1 * W0GATE + cg * W0ROW;
    const float* wh0p = sm + 2 * W0GATE + cg * W0ROW;
    const float* wr1p = sm + SM_W1 + 0 * W1GATE + cg * W1ROW;
    const float* wz1p = sm + SM_W1 + 1 * W1GATE + cg * W1ROW;
    const float* wh1p = sm + SM_W1 + 2 * W1GATE + cg * W1ROW;
    float vbr1 = br1[n], vbz1 = bz1[n], vbh1 = bh1[n];
    float* sA = sm + SM_SA;
    __syncthreads();

    float rg[32];
    float z0a = 0.f, z0b = 0.f, h0oa = 0.f, h0ob = 0.f;
    float z1a = 0.f, z1b = 0.f, h1oa = 0.f, h1ob = 0.f;

    // Tick u: PhA = gates(L0 @ t=u; L1 @ t=u-1) incl. Wh1hi*h0c partial
    //         PhB = candidates + state updates
    for (int u = 0; u <= S_; ++u) {
        const float* h0c = g_h0[u & 1];           // h0(u-1)
        float* h0n = g_h0[(u & 1) ^ 1];           // h0(u) dest
        const float* h1c = g_h1[(u + 1) & 1];     // h1(u-2)
        float* h1n = g_h1[u & 1];                 // h1(u-1) dest
        size_t xo = ((size_t)u * H_ + n) * B_;

        ull pr0[4] = {0,0,0,0}, pz0[4] = {0,0,0,0};
        ull pr1[4] = {0,0,0,0}, pz1[4] = {0,0,0,0};
        ull ph1[4] = {0,0,0,0};                   // carried into PhB

        // ======== PhA: h0c (4 chunks, 5-gate) then h1c (4 chunks, 2-gate) ========
        gather32(rg, h0c);
        sts32(sA, rg);
        __syncthreads();
        #pragma unroll
        for (int c = 0; c < 8; c++) {
            if (c < 7) {
                const float* nsrc = (c + 1 < 4) ? (h0c + (c + 1) * KC * B_)
                                                : (h1c + (c + 1 - 4) * KC * B_);
                gather32(rg, nsrc);
            }
            float* buf = sA + (c & 1) * SABUF;
            const float* a0 = buf + b0 * SAROW;
            const float* a1 = buf + b1 * SAROW;
            if (c < 4) {
                int ko = c * KC;
                dot5_2r(a0, a1, wr0p + ko, wz0p + ko, wr1p + H_ + ko, wz1p + H_ + ko,
                        wh1p + H_ + ko, pr0, pz0, pr1, pz1, ph1);
            } else {
                int ko = (c - 4) * KC;
                dot2_2r(a0, a1, wr1p + ko, wz1p + ko, pr1, pz1);
            }
            if (c < 7) sts32(sA + ((c + 1) & 1) * SABUF, rg);
            __syncthreads();
        }
        if (u < S_) {
            size_t x1o = (size_t)S_ * H_ * B_;
            float ra = sigmoidf_(upk(pr0[0]) + upk(pr0[1]) + g_Xp[xo + b0]);
            float rb = sigmoidf_(upk(pr0[2]) + upk(pr0[3]) + g_Xp[xo + b1]);
            z0a = sigmoidf_(upk(pz0[0]) + upk(pz0[1]) + g_Xp[x1o + xo + b0]);
            z0b = sigmoidf_(upk(pz0[2]) + upk(pz0[3]) + g_Xp[x1o + xo + b1]);
            h0oa = __ldcg(h0c + n * B_ + b0);
            h0ob = __ldcg(h0c + n * B_ + b1);
            g_rh0[n * B_ + b0] = ra * h0oa;
            g_rh0[n * B_ + b1] = rb * h0ob;
        }
        if (u > 0) {
            float ra = sigmoidf_(upk(pr1[0]) + upk(pr1[1]) + vbr1);
            float rb = sigmoidf_(upk(pr1[2]) + upk(pr1[3]) + vbr1);
            z1a = sigmoidf_(upk(pz1[0]) + upk(pz1[1]) + vbz1);
            z1b = sigmoidf_(upk(pz1[2]) + upk(pz1[3]) + vbz1);
            h1oa = __ldcg(h1c + n * B_ + b0);
            h1ob = __ldcg(h1c + n * B_ + b1);
            g_rh1[n * B_ + b0] = ra * h1oa;
            g_rh1[n * B_ + b1] = rb * h1ob;
        }
        grid_barrier();

        // ======== PhB: rh0 (4 chunks, Wh0) then rh1 (4 chunks, Wh1 lo) ========
        ull ph0[4] = {0,0,0,0};
        gather32(rg, g_rh0);
        sts32(sA, rg);
        __syncthreads();
        #pragma unroll
        for (int c = 0; c < 8; c++) {
            if (c < 7) {
                const float* nsrc = (c + 1 < 4) ? (g_rh0 + (c + 1) * KC * B_)
                                                : (g_rh1 + (c + 1 - 4) * KC * B_);
                gather32(rg, nsrc);
            }
            float* buf = sA + (c & 1) * SABUF;
            const float* a0 = buf + b0 * SAROW;
            const float* a1 = buf + b1 * SAROW;
            if (c < 4) dot1_2r(a0, a1, wh0p + c * KC, ph0);
            else       dot1_2r(a0, a1, wh1p + (c - 4) * KC, ph1);
            if (c < 7) sts32(sA + ((c + 1) & 1) * SABUF, rg);
            __syncthreads();
        }
        if (u < S_) {
            size_t x2o = 2 * (size_t)S_ * H_ * B_;
            float hta = tanhf(upk(ph0[0]) + upk(ph0[1]) + g_Xp[x2o + xo + b0]);
            float htb = tanhf(upk(ph0[2]) + upk(ph0[3]) + g_Xp[x2o + xo + b1]);
            h0n[n * B_ + b0] = (1.f - z0a) * h0oa + z0a * hta;
            h0n[n * B_ + b1] = (1.f - z0b) * h0ob + z0b * htb;
        }
        if (u > 0) {
            float hta = tanhf(upk(ph1[0]) + upk(ph1[1]) + vbh1);
            float htb = tanhf(upk(ph1[2]) + upk(ph1[3]) + vbh1);
            float h1na = (1.f - z1a) * h1oa + z1a * hta;
            float h1nb = (1.f - z1b) * h1ob + z1b * htb;
            h1n[n * B_ + b0] = h1na;
            h1n[n * B_ + b1] = h1nb;
            g_H1[((size_t)(u - 1) * B_ + b0) * H_ + n] = h1na;
            g_H1[((size_t)(u - 1) * B_ + b1) * H_ + n] = h1nb;
        }
        grid_barrier();
        if (u > 0 && blockIdx.x == 0 && tid == 0) {
            __threadfence();
            atomicExch(&g_progress, u - 1);
        }
    }
}

// ---------------- logits role: tile-queue consumers (256 thr, from R6) ----------
__device__ void logits_role(float* sm, const float* __restrict__ Wy,
                            const float* __restrict__ by, float* __restrict__ out) {
    float* As = sm;                 // [16][128]
    float* Bs = sm + 2048;          // [16][128]
    int* s_idx = (int*)(sm + 4096);
    int tid = threadIdx.x;
    int w = tid >> 5, l = tid & 31;
    int tx = (w & 1) * 8 + (l & 7);      // 0..15
    int ty = (w >> 1) * 4 + (l >> 3);    // 0..15
    const float* A = g_H1;

    while (true) {
        if (tid == 0) *s_idx = atomicAdd(&g_tile_ctr, 1);
        __syncthreads();
        int idx = *s_idx;
        __syncthreads();
        if (idx >= NTM * NTN) break;
        int mtile = idx / NTN, ntile = idx % NTN;
        int m0 = mtile * 128, n0 = ntile * 128;
        int need = mtile * 2 + 1;
        if (tid == 0) {
            while (*((volatile int*)&g_progress) < need) { __nanosleep(200); }
        }
        __syncthreads();
        __threadfence();

        ull acc2[8][4];
        #pragma unroll
        for (int i = 0; i < 8; i++)
            #pragma unroll
            for (int j = 0; j < 4; j++) acc2[i][j] = 0ull;

        for (int k0 = 0; k0 < H_; k0 += 16) {
            #pragma unroll
            for (int r = 0; r < 2; r++) {
                int f = tid + r * 256;
                int row = f >> 2, q = f & 3;
                float4 v = *(const float4*)&A[(size_t)(m0 + row) * H_ + k0 + q * 4];
                As[(q * 4 + 0) * 128 + row] = v.x; As[(q * 4 + 1) * 128 + row] = v.y;
                As[(q * 4 + 2) * 128 + row] = v.z; As[(q * 4 + 3) * 128 + row] = v.w;
            }
            #pragma unroll
            for (int r = 0; r < 2; r++) {
                int f = tid + r * 256;
                int row = f >> 2, q = f & 3;
                int nn = n0 + row;
                float4 v = make_float4(0.f, 0.f, 0.f, 0.f);
                if (nn < V_) v = *(const float4*)&Wy[(size_t)nn * H_ + k0 + q * 4];
                Bs[(q * 4 + 0) * 128 + row] = v.x; Bs[(q * 4 + 1) * 128 + row] = v.y;
                Bs[(q * 4 + 2) * 128 + row] = v.z; Bs[(q * 4 + 3) * 128 + row] = v.w;
            }
            __syncthreads();
            #pragma unroll
            for (int kk = 0; kk < 16; kk++) {
                float a[8];
                *(float4*)&a[0] = *(const float4*)&As[kk * 128 + ty * 4];
                *(float4*)&a[4] = *(const float4*)&As[kk * 128 + 64 + ty * 4];
                ulonglong2 bv0 = *(const ulonglong2*)&Bs[kk * 128 + tx * 4];
                ulonglong2 bv1 = *(const ulonglong2*)&Bs[kk * 128 + 64 + tx * 4];
                #pragma unroll
                for (int i = 0; i < 8; i++) {
                    ull ad = dup2(a[i]);
                    fma2(acc2[i][0], ad, bv0.x);
                    fma2(acc2[i][1], ad, bv0.y);
                    fma2(acc2[i][2], ad, bv1.x);
                    fma2(acc2[i][3], ad, bv1.y);
                }
            }
            __syncthreads();
        }
        #pragma unroll
        for (int i = 0; i < 8; i++) {
            int rloc = (i < 4) ? (ty * 4 + i) : (64 + ty * 4 + i - 4);
            size_t row = (size_t)m0 + rloc;
            #pragma unroll
            for (int jp = 0; jp < 4; jp++) {
                int v0 = n0 + ((jp < 2) ? (tx * 4 + jp * 2) : (64 + tx * 4 + (jp - 2) * 2));
                float lo = __uint_as_float((unsigned)acc2[i][jp]);
                float hi = __uint_as_float((unsigned)(acc2[i][jp] >> 32));
                if (v0 < V_)     out[row * V_ + v0]     = lo + by[v0];
                if (v0 + 1 < V_) out[row * V_ + v0 + 1] = hi + by[v0 + 1];
            }
        }
    }
}

// ---------------- fused kernel ----------------
__global__ void __launch_bounds__(TPB)
fused_kernel(const float* __restrict__ Wr0, const float* __restrict__ Wz0,
             const float* __restrict__ Wh0,
             const float* __restrict__ Wr1, const float* __restrict__ Wz1,
             const float* __restrict__ Wh1,
             const float* __restrict__ br1, const float* __restrict__ bz1,
             const float* __restrict__ bh1,
             const float* __restrict__ Wy, const float* __restrict__ by,
             float* __restrict__ out) {
    extern __shared__ float sm[];
    if (blockIdx.x < NB) {
        recurrence_role(sm, Wr0, Wz0, Wh0, Wr1, Wz1, Wh1, br1, bz1, bh1);
        __syncthreads();
    }
    logits_role(sm, Wy, by, out);
}

// ---------------- launch ----------------
extern "C" void kernel_launch(void* const* d_in, const int* in_sizes, int n_in,
                              void* d_out, int out_size) {
    const int*   inputs = (const int*)d_in[0];
    const float* hidden = (const float*)d_in[1];
    const float* emb    = (const float*)d_in[2];
    const float* W_r0 = (const float*)d_in[3];
    const float* b_r0 = (const float*)d_in[4];
    const float* W_z0 = (const float*)d_in[5];
    const float* b_z0 = (const float*)d_in[6];
    const float* W_h0 = (const float*)d_in[7];
    const float* b_h0 = (const float*)d_in[8];
    const float* W_r1 = (const float*)d_in[9];
    const float* b_r1 = (const float*)d_in[10];
    const float* W_z1 = (const float*)d_in[11];
    const float* b_z1 = (const float*)d_in[12];
    const float* W_h1 = (const float*)d_in[13];
    const float* b_h1 = (const float*)d_in[14];
    const float* Wy   = (const float*)d_in[15];
    const float* by   = (const float*)d_in[16];
    float* out = (float*)d_out;

    cudaFuncSetAttribute(fused_kernel, cudaFuncAttributeMaxDynamicSharedMemorySize,
                         SMEM_BYTES);

    xproj_gemm<<<dim3(3 * H_ / 128, (S_ * B_) / 128), 256>>>(inputs, emb, W_r0, W_z0, W_h0,
                                                             b_r0, b_z0, b_h0);
    init_hidden_kernel<<<(B_ * H_ + 255) / 256, 256>>>(hidden);
    fused_kernel<<<NCTA, TPB, SMEM_BYTES>>>(W_r0, W_z0, W_h0, W_r1, W_z1, W_h1,
                                            b_r1, b_z1, b_h1, Wy, by, out);

    long long logits_elems = (long long)S_ * B_ * V_;
    if ((long long)out_size >= logits_elems + 2LL * B_ * H_) {
        write_hidden_kernel<<<(B_ * H_ + 255) / 256, 256>>>(out, logits_elems);
    }
}

// round 11
// speedup vs baseline: 1.5955x; 1.0450x over previous
#include <cuda_runtime.h>
#include <math.h>

// Problem constants
#define S_ 128
#define B_ 64
#define V_ 10000
#define E_ 256
#define H_ 512

// Fused kernel config
#define NB 64            // recurrence CTAs (1/SM, co-resident)
#define NCTA 148         // total CTAs
#define TPB 256
#define KC 128
#define NTN 79           // logits n-tiles
#define NTM 64           // logits m-tiles

typedef unsigned long long ull;

// ---------------- device scratch ----------------
// State layout [k][b] (k-major), ping-pong buffers.
__device__ float g_h0[2][H_ * B_];
__device__ float g_h1[2][H_ * B_];
__device__ float g_rh0[H_ * B_];
__device__ float g_rh1[H_ * B_];
__device__ float g_Xp[3u * S_ * H_ * B_];    // [gate][t][n][b]
__device__ float g_H1[(size_t)S_ * B_ * H_]; // [t*B+b][k]
__device__ unsigned g_bar_count = 0;
__device__ unsigned g_genv[16 * 32];
__device__ int g_progress;
__device__ int g_tile_ctr;

// ---------------- packed f32x2 helpers ----------------
__device__ __forceinline__ void fma2(ull& acc, ull a, ull w) {
    asm("fma.rn.f32x2 %0, %1, %2, %0;" : "+l"(acc) : "l"(a), "l"(w));
}
__device__ __forceinline__ float upk(ull v) {
    return __uint_as_float((unsigned)v) + __uint_as_float((unsigned)(v >> 32));
}
__device__ __forceinline__ ull dup2(float f) {
    ull d;
    asm("mov.b64 %0, {%1, %1};" : "=l"(d) : "r"(__float_as_uint(f)));
    return d;
}
__device__ __forceinline__ float sigmoidf_(float x) { return 1.0f / (1.0f + expf(-x)); }

// ---------------- grid barrier (NB recurrence CTAs only) ----------------
__device__ __forceinline__ void grid_barrier() {
    __syncthreads();
    if (threadIdx.x == 0) {
        __threadfence();
        unsigned slot = (blockIdx.x & 15) * 32;
        unsigned old = *((volatile unsigned*)&g_genv[slot]);
        unsigned t = atomicAdd(&g_bar_count, 1u);
        if (t == NB - 1) {
            g_bar_count = 0;
            __threadfence();
            #pragma unroll
            for (int i = 0; i < 16; i++)
                *((volatile unsigned*)&g_genv[i * 32]) = old + 1;
        } else {
            while (*((volatile unsigned*)&g_genv[slot]) == old) { }
        }
        __threadfence();
    }
    __syncthreads();
}

// ---------------- recurrence smem layout ----------------
#define W0ROW 516
#define W1ROW 1028
#define W0GATE (8 * W0ROW)
#define W1GATE (8 * W1ROW)
#define SM_W1 (3 * W0GATE)                   // 12384
#define SM_SA (SM_W1 + 3 * W1GATE)           // 37056
#define SAROW 132
#define SABUF (B_ * SAROW)                   // 8448
#define SM_FLOATS (SM_SA + 2 * SABUF)        // 53952
#define SMEM_BYTES (SM_FLOATS * 4)           // 215808

// ---------------- staging: global [k][b] -> regs -> smem [b][k] ----------------
__device__ __forceinline__ void gather32(float* rg, const float* __restrict__ src) {
    int sb = threadIdx.x & 63;
    int kq = threadIdx.x >> 6;               // 0..3, 32 k each
    const float* s = src + kq * 32 * B_ + sb;
    #pragma unroll
    for (int i = 0; i < 32; i++) rg[i] = __ldcg(s + i * B_);
}
__device__ __forceinline__ void sts32(float* buf, const float* rg) {
    int sb = threadIdx.x & 63;
    int kq = threadIdx.x >> 6;
    float* d = buf + sb * SAROW + kq * 32;
    #pragma unroll
    for (int i = 0; i < 32; i += 4)
        *(float4*)(d + i) = make_float4(rg[i], rg[i + 1], rg[i + 2], rg[i + 3]);
}

// ---------------- fused chunk dot products (2 b-rows per thread) ----------------
__device__ __forceinline__ void dot5_2r(const float* __restrict__ a0,
                                        const float* __restrict__ a1,
                                        const float* __restrict__ w0r,
                                        const float* __restrict__ w0z,
                                        const float* __restrict__ w1r,
                                        const float* __restrict__ w1z,
                                        const float* __restrict__ w1h,
                                        ull* pr0, ull* pz0,
                                        ull* pr1, ull* pz1, ull* ph1) {
    #pragma unroll 8
    for (int kk = 0; kk < KC; kk += 4) {
        ulonglong2 x0 = *(const ulonglong2*)(a0 + kk);
        ulonglong2 x1 = *(const ulonglong2*)(a1 + kk);
        ulonglong2 wa = *(const ulonglong2*)(w0r + kk);
        ulonglong2 wb = *(const ulonglong2*)(w0z + kk);
        ulonglong2 wc = *(const ulonglong2*)(w1r + kk);
        ulonglong2 wd = *(const ulonglong2*)(w1z + kk);
        ulonglong2 we = *(const ulonglong2*)(w1h + kk);
        fma2(pr0[0], x0.x, wa.x); fma2(pr0[1], x0.y, wa.y);
        fma2(pr0[2], x1.x, wa.x); fma2(pr0[3], x1.y, wa.y);
        fma2(pz0[0], x0.x, wb.x); fma2(pz0[1], x0.y, wb.y);
        fma2(pz0[2], x1.x, wb.x); fma2(pz0[3], x1.y, wb.y);
        fma2(pr1[0], x0.x, wc.x); fma2(pr1[1], x0.y, wc.y);
        fma2(pr1[2], x1.x, wc.x); fma2(pr1[3], x1.y, wc.y);
        fma2(pz1[0], x0.x, wd.x); fma2(pz1[1], x0.y, wd.y);
        fma2(pz1[2], x1.x, wd.x); fma2(pz1[3], x1.y, wd.y);
        fma2(ph1[0], x0.x, we.x); fma2(ph1[1], x0.y, we.y);
        fma2(ph1[2], x1.x, we.x); fma2(ph1[3], x1.y, we.y);
    }
}
__device__ __forceinline__ void dot2_2r(const float* __restrict__ a0,
                                        const float* __restrict__ a1,
                                        const float* __restrict__ wr,
                                        const float* __restrict__ wz,
                                        ull* pr, ull* pz) {
    #pragma unroll 8
    for (int kk = 0; kk < KC; kk += 4) {
        ulonglong2 x0 = *(const ulonglong2*)(a0 + kk);
        ulonglong2 x1 = *(const ulonglong2*)(a1 + kk);
        ulonglong2 w1 = *(const ulonglong2*)(wr + kk);
        ulonglong2 w2 = *(const ulonglong2*)(wz + kk);
        fma2(pr[0], x0.x, w1.x); fma2(pr[1], x0.y, w1.y);
        fma2(pr[2], x1.x, w1.x); fma2(pr[3], x1.y, w1.y);
        fma2(pz[0], x0.x, w2.x); fma2(pz[1], x0.y, w2.y);
        fma2(pz[2], x1.x, w2.x); fma2(pz[3], x1.y, w2.y);
    }
}
__device__ __forceinline__ void dot1_2r(const float* __restrict__ a0,
                                        const float* __restrict__ a1,
                                        const float* __restrict__ w, ull* p) {
    #pragma unroll 8
    for (int kk = 0; kk < KC; kk += 4) {
        ulonglong2 x0 = *(const ulonglong2*)(a0 + kk);
        ulonglong2 x1 = *(const ulonglong2*)(a1 + kk);
        ulonglong2 wv = *(const ulonglong2*)(w + kk);
        fma2(p[0], x0.x, wv.x); fma2(p[1], x0.y, wv.y);
        fma2(p[2], x1.x, wv.x); fma2(p[3], x1.y, wv.y);
    }
}

// ---------------- init / finalize / marker ----------------
__global__ void init_hidden_kernel(const float* __restrict__ hidden) {
    int i = blockIdx.x * blockDim.x + threadIdx.x;
    if (i < B_ * H_) {
        int b = i / H_, k = i % H_;
        g_h0[0][k * B_ + b] = hidden[i];
        g_h1[0][k * B_ + b] = hidden[B_ * H_ + i];
    }
    if (blockIdx.x == 0 && threadIdx.x == 0) {
        g_progress = -1;
        g_tile_ctr = 0;
    }
}
__global__ void dummy_mark() {}   // positions fused_kernel as 4th launch for ncu
__global__ void write_hidden_kernel(float* __restrict__ out, long long off) {
    int i = blockIdx.x * blockDim.x + threadIdx.x;
    if (i < B_ * H_) {
        int b = i / H_, k = i % H_;
        out[off + i] = g_h0[0][k * B_ + b];            // finals land in buf 0
        out[off + B_ * H_ + i] = g_h1[0][k * B_ + b];
    }
}

// ---------------- xproj GEMM: Xp_g[t][n][b] = emb(tok) @ Wg0[:,H:]^T + bg0 -------
__global__ void xproj_gemm(const int* __restrict__ tok, const float* __restrict__ emb,
                           const float* __restrict__ Wr0, const float* __restrict__ Wz0,
                           const float* __restrict__ Wh0,
                           const float* __restrict__ br0, const float* __restrict__ bz0,
                           const float* __restrict__ bh0) {
    __shared__ float As[16][128];
    __shared__ float Bs[16][128];
    __shared__ int stok[128];
    int n0 = blockIdx.x * 128;
    int m0 = blockIdx.y * 128;
    int g = n0 / H_;
    int nb = n0 % H_;
    const float* W = (g == 0) ? Wr0 : (g == 1) ? Wz0 : Wh0;
    const float* bias = (g == 0) ? br0 : (g == 1) ? bz0 : bh0;
    int tid = threadIdx.x;
    if (tid < 128) stok[tid] = tok[m0 + tid];
    __syncthreads();
    int tx = tid % 16, ty = tid / 16;
    float acc[8][8];
    #pragma unroll
    for (int i = 0; i < 8; i++)
        #pragma unroll
        for (int j = 0; j < 8; j++) acc[i][j] = 0.f;

    for (int k0 = 0; k0 < E_; k0 += 16) {
        #pragma unroll
        for (int r = 0; r < 2; r++) {
            int f = tid + r * 256;
            int row = f >> 2, q = f & 3;
            int t = stok[row];
            float4 v = *(const float4*)&emb[(size_t)t * E_ + k0 + q * 4];
            As[q * 4 + 0][row] = v.x; As[q * 4 + 1][row] = v.y;
            As[q * 4 + 2][row] = v.z; As[q * 4 + 3][row] = v.w;
        }
        #pragma unroll
        for (int r = 0; r < 2; r++) {
            int f = tid + r * 256;
            int row = f >> 2, q = f & 3;
            float4 v = *(const float4*)&W[(size_t)(nb + row) * (H_ + E_) + H_ + k0 + q * 4];
            Bs[q * 4 + 0][row] = v.x; Bs[q * 4 + 1][row] = v.y;
            Bs[q * 4 + 2][row] = v.z; Bs[q * 4 + 3][row] = v.w;
        }
        __syncthreads();
        #pragma unroll
        for (int kk = 0; kk < 16; kk++) {
            float a[8], bv[8];
            *(float4*)&a[0] = *(const float4*)&As[kk][ty * 8];
            *(float4*)&a[4] = *(const float4*)&As[kk][ty * 8 + 4];
            *(float4*)&bv[0] = *(const float4*)&Bs[kk][tx * 8];
            *(float4*)&bv[4] = *(const float4*)&Bs[kk][tx * 8 + 4];
            #pragma unroll
            for (int i = 0; i < 8; i++)
                #pragma unroll
                for (int j = 0; j < 8; j++) acc[i][j] = fmaf(a[i], bv[j], acc[i][j]);
        }
        __syncthreads();
    }
    float bfrag[8];
    *(float4*)&bfrag[0] = *(const float4*)&bias[nb + tx * 8];
    *(float4*)&bfrag[4] = *(const float4*)&bias[nb + tx * 8 + 4];
    float* Xg = g_Xp + (size_t)g * S_ * H_ * B_;
    #pragma unroll
    for (int i = 0; i < 8; i++) {
        int row = m0 + ty * 8 + i;
        int t = row >> 6, b = row & 63;
        #pragma unroll
        for (int j = 0; j < 8; j++) {
            int n = nb + tx * 8 + j;
            Xg[((size_t)t * H_ + n) * B_ + b] = acc[i][j] + bfrag[j];
        }
    }
}

// ---------------- recurrence role: 256 thr, fused gates, 2-deep prefetch ---------
__device__ void recurrence_role(float* sm,
                  const float* __restrict__ Wr0, const float* __restrict__ Wz0,
                  const float* __restrict__ Wh0,
                  const float* __restrict__ Wr1, const float* __restrict__ Wz1,
                  const float* __restrict__ Wh1,
                  const float* __restrict__ br1, const float* __restrict__ bz1,
                  const float* __restrict__ bh1) {
    int tid = threadIdx.x;
    int n0 = blockIdx.x * 8;
    int cg = tid & 7;
    int bp = tid >> 3;           // 0..31
    int b0 = bp * 2, b1 = b0 + 1;
    int n = n0 + cg;

    // -------- preload weights --------
    for (int j = tid; j < 3072; j += TPB) {               // L0 h-part: 3x8x128 float4
        int g = j >> 10, rem = j & 1023;
        int r = rem >> 7, k4 = rem & 127;
        const float* Ws = (g == 0) ? Wr0 : (g == 1) ? Wz0 : Wh0;
        *(float4*)(sm + g * W0GATE + r * W0ROW + k4 * 4) =
            *(const float4*)&Ws[(size_t)(n0 + r) * (H_ + E_) + k4 * 4];
    }
    for (int j = tid; j < 6144; j += TPB) {               // L1: 3x8x256 float4
        int g = j >> 11, rem = j & 2047;
        int r = rem >> 8, k4 = rem & 255;
        const float* Ws = (g == 0) ? Wr1 : (g == 1) ? Wz1 : Wh1;
        *(float4*)(sm + SM_W1 + g * W1GATE + r * W1ROW + k4 * 4) =
            *(const float4*)&Ws[(size_t)(n0 + r) * 1024 + k4 * 4];
    }
    const float* wr0p = sm + 0 * W0GATE + cg * W0ROW;
    const float* wz0p = sm + 1 * W0GATE + cg * W0ROW;
    const float* wh0p = sm + 2 * W0GATE + cg * W0ROW;
    const float* wr1p = sm + SM_W1 + 0 * W1GATE + cg * W1ROW;
    const float* wz1p = sm + SM_W1 + 1 * W1GATE + cg * W1ROW;
    const float* wh1p = sm + SM_W1 + 2 * W1GATE + cg * W1ROW;
    float vbr1 = br1[n], vbz1 = bz1[n], vbh1 = bh1[n];
    float* sA = sm + SM_SA;
    __syncthreads();

    float rgA[32], rgB[32];
    float z0a = 0.f, z0b = 0.f, h0oa = 0.f, h0ob = 0.f;
    float z1a = 0.f, z1b = 0.f, h1oa = 0.f, h1ob = 0.f;

    for (int u = 0; u <= S_; ++u) {
        const float* h0c = g_h0[u & 1];           // h0(u-1)
        float* h0n = g_h0[(u & 1) ^ 1];           // h0(u) dest
        const float* h1c = g_h1[(u + 1) & 1];     // h1(u-2)
        float* h1n = g_h1[u & 1];                 // h1(u-1) dest
        int ue = (u < S_) ? u : (S_ - 1);         // clamp for safe Xp prefetch
        size_t xo = ((size_t)ue * H_ + n) * B_;
        size_t x1o = (size_t)S_ * H_ * B_;
        size_t x2o = 2 * (size_t)S_ * H_ * B_;

        ull pr0[4] = {0,0,0,0}, pz0[4] = {0,0,0,0};
        ull pr1[4] = {0,0,0,0}, pz1[4] = {0,0,0,0};
        ull ph1[4] = {0,0,0,0};                   // carried into PhB

        // ---- hoisted scalar prefetch (overlaps chunk loop) ----
        float xra = __ldcg(&g_Xp[xo + b0]);
        float xrb = __ldcg(&g_Xp[xo + b1]);
        float xza = __ldcg(&g_Xp[x1o + xo + b0]);
        float xzb = __ldcg(&g_Xp[x1o + xo + b1]);
        float xha = __ldcg(&g_Xp[x2o + xo + b0]);
        float xhb = __ldcg(&g_Xp[x2o + xo + b1]);
        h0oa = __ldcg(h0c + n * B_ + b0);
        h0ob = __ldcg(h0c + n * B_ + b1);
        h1oa = __ldcg(h1c + n * B_ + b0);
        h1ob = __ldcg(h1c + n * B_ + b1);

        // ======== PhA: h0c (4 chunks, 5-gate) then h1c (4 chunks, 2-gate) ========
        // 2-deep prefetch: gather chunk c+2 while computing chunk c.
        gather32(rgA, h0c);
        gather32(rgB, h0c + KC * B_);
        sts32(sA, rgA);
        __syncthreads();
        #pragma unroll
        for (int cp = 0; cp < 4; cp++) {
            {   // even chunk c = 2*cp  (buf0; rgA free -> gathers c+2; rgB holds c+1)
                const int c = 2 * cp;
                if (c + 2 < 8) {
                    const float* nsrc = (c + 2 < 4) ? (h0c + (c + 2) * KC * B_)
                                                    : (h1c + (c + 2 - 4) * KC * B_);
                    gather32(rgA, nsrc);
                }
                const float* a0 = sA + b0 * SAROW;
                const float* a1 = sA + b1 * SAROW;
                if (c < 4) {
                    int ko = c * KC;
                    dot5_2r(a0, a1, wr0p + ko, wz0p + ko, wr1p + H_ + ko,
                            wz1p + H_ + ko, wh1p + H_ + ko, pr0, pz0, pr1, pz1, ph1);
                } else {
                    int ko = (c - 4) * KC;
                    dot2_2r(a0, a1, wr1p + ko, wz1p + ko, pr1, pz1);
                }
                sts32(sA + SABUF, rgB);
                __syncthreads();
            }
            {   // odd chunk c = 2*cp+1 (buf1; rgB free -> gathers c+2; rgA holds c+1)
                const int c = 2 * cp + 1;
                if (c + 2 < 8) {
                    const float* nsrc = (c + 2 < 4) ? (h0c + (c + 2) * KC * B_)
                                                    : (h1c + (c + 2 - 4) * KC * B_);
                    gather32(rgB, nsrc);
                }
                const float* a0 = sA + SABUF + b0 * SAROW;
                const float* a1 = sA + SABUF + b1 * SAROW;
                if (c < 4) {
                    int ko = c * KC;
                    dot5_2r(a0, a1, wr0p + ko, wz0p + ko, wr1p + H_ + ko,
                            wz1p + H_ + ko, wh1p + H_ + ko, pr0, pz0, pr1, pz1, ph1);
                } else {
                    int ko = (c - 4) * KC;
                    dot2_2r(a0, a1, wr1p + ko, wz1p + ko, pr1, pz1);
                }
                if (c + 1 < 8) sts32(sA, rgA);
                __syncthreads();
            }
        }
        if (u < S_) {
            float ra = sigmoidf_(upk(pr0[0]) + upk(pr0[1]) + xra);
            float rb = sigmoidf_(upk(pr0[2]) + upk(pr0[3]) + xrb);
            z0a = sigmoidf_(upk(pz0[0]) + upk(pz0[1]) + xza);
            z0b = sigmoidf_(upk(pz0[2]) + upk(pz0[3]) + xzb);
            g_rh0[n * B_ + b0] = ra * h0oa;
            g_rh0[n * B_ + b1] = rb * h0ob;
        }
        if (u > 0) {
            float ra = sigmoidf_(upk(pr1[0]) + upk(pr1[1]) + vbr1);
            float rb = sigmoidf_(upk(pr1[2]) + upk(pr1[3]) + vbr1);
            z1a = sigmoidf_(upk(pz1[0]) + upk(pz1[1]) + vbz1);
            z1b = sigmoidf_(upk(pz1[2]) + upk(pz1[3]) + vbz1);
            g_rh1[n * B_ + b0] = ra * h1oa;
            g_rh1[n * B_ + b1] = rb * h1ob;
        }
        grid_barrier();

        // ======== PhB: rh0 (4 chunks, Wh0) then rh1 (4 chunks, Wh1 lo) ========
        ull ph0[4] = {0,0,0,0};
        gather32(rgA, g_rh0);
        gather32(rgB, g_rh0 + KC * B_);
        sts32(sA, rgA);
        __syncthreads();
        #pragma unroll
        for (int cp = 0; cp < 4; cp++) {
            {   // even chunk c = 2*cp
                const int c = 2 * cp;
                if (c + 2 < 8) {
                    const float* nsrc = (c + 2 < 4) ? (g_rh0 + (c + 2) * KC * B_)
                                                    : (g_rh1 + (c + 2 - 4) * KC * B_);
                    gather32(rgA, nsrc);
                }
                const float* a0 = sA + b0 * SAROW;
                const float* a1 = sA + b1 * SAROW;
                if (c < 4) dot1_2r(a0, a1, wh0p + c * KC, ph0);
                else       dot1_2r(a0, a1, wh1p + (c - 4) * KC, ph1);
                sts32(sA + SABUF, rgB);
                __syncthreads();
            }
            {   // odd chunk c = 2*cp+1
                const int c = 2 * cp + 1;
                if (c + 2 < 8) {
                    const float* nsrc = (c + 2 < 4) ? (g_rh0 + (c + 2) * KC * B_)
                                                    : (g_rh1 + (c + 2 - 4) * KC * B_);
                    gather32(rgB, nsrc);
                }
                const float* a0 = sA + SABUF + b0 * SAROW;
                const float* a1 = sA + SABUF + b1 * SAROW;
                if (c < 4) dot1_2r(a0, a1, wh0p + c * KC, ph0);
                else       dot1_2r(a0, a1, wh1p + (c - 4) * KC, ph1);
                if (c + 1 < 8) sts32(sA, rgA);
                __syncthreads();
            }
        }
        if (u < S_) {
            float hta = tanhf(upk(ph0[0]) + upk(ph0[1]) + xha);
            float htb = tanhf(upk(ph0[2]) + upk(ph0[3]) + xhb);
            h0n[n * B_ + b0] = (1.f - z0a) * h0oa + z0a * hta;
            h0n[n * B_ + b1] = (1.f - z0b) * h0ob + z0b * htb;
        }
        if (u > 0) {
            float hta = tanhf(upk(ph1[0]) + upk(ph1[1]) + vbh1);
            float htb = tanhf(upk(ph1[2]) + upk(ph1[3]) + vbh1);
            float h1na = (1.f - z1a) * h1oa + z1a * hta;
            float h1nb = (1.f - z1b) * h1ob + z1b * htb;
            h1n[n * B_ + b0] = h1na;
            h1n[n * B_ + b1] = h1nb;
            g_H1[((size_t)(u - 1) * B_ + b0) * H_ + n] = h1na;
            g_H1[((size_t)(u - 1) * B_ + b1) * H_ + n] = h1nb;
        }
        grid_barrier();
        if (u > 0 && blockIdx.x == 0 && tid == 0) {
            __threadfence();
            atomicExch(&g_progress, u - 1);
        }
    }
}

// ---------------- logits role: tile-queue consumers (256 thr) ----------------
__device__ void logits_role(float* sm, const float* __restrict__ Wy,
                            const float* __restrict__ by, float* __restrict__ out) {
    float* As = sm;                 // [16][128]
    float* Bs = sm + 2048;          // [16][128]
    int* s_idx = (int*)(sm + 4096);
    int tid = threadIdx.x;
    int w = tid >> 5, l = tid & 31;
    int tx = (w & 1) * 8 + (l & 7);      // 0..15
    int ty = (w >> 1) * 4 + (l >> 3);    // 0..15
    const float* A = g_H1;

    while (true) {
        if (tid == 0) *s_idx = atomicAdd(&g_tile_ctr, 1);
        __syncthreads();
        int idx = *s_idx;
        __syncthreads();
        if (idx >= NTM * NTN) break;
        int mtile = idx / NTN, ntile = idx % NTN;
        int m0 = mtile * 128, n0 = ntile * 128;
        int need = mtile * 2 + 1;
        if (tid == 0) {
            while (*((volatile int*)&g_progress) < need) { __nanosleep(200); }
        }
        __syncthreads();
        __threadfence();

        ull acc2[8][4];
        #pragma unroll
        for (int i = 0; i < 8; i++)
            #pragma unroll
            for (int j = 0; j < 4; j++) acc2[i][j] = 0ull;

        for (int k0 = 0; k0 < H_; k0 += 16) {
            #pragma unroll
            for (int r = 0; r < 2; r++) {
                int f = tid + r * 256;
                int row = f >> 2, q = f & 3;
                float4 v = *(const float4*)&A[(size_t)(m0 + row) * H_ + k0 + q * 4];
                As[(q * 4 + 0) * 128 + row] = v.x; As[(q * 4 + 1) * 128 + row] = v.y;
                As[(q * 4 + 2) * 128 + row] = v.z; As[(q * 4 + 3) * 128 + row] = v.w;
            }
            #pragma unroll
            for (int r = 0; r < 2; r++) {
                int f = tid + r * 256;
                int row = f >> 2, q = f & 3;
                int nn = n0 + row;
                float4 v = make_float4(0.f, 0.f, 0.f, 0.f);
                if (nn < V_) v = *(const float4*)&Wy[(size_t)nn * H_ + k0 + q * 4];
                Bs[(q * 4 + 0) * 128 + row] = v.x; Bs[(q * 4 + 1) * 128 + row] = v.y;
                Bs[(q * 4 + 2) * 128 + row] = v.z; Bs[(q * 4 + 3) * 128 + row] = v.w;
            }
            __syncthreads();
            #pragma unroll
            for (int kk = 0; kk < 16; kk++) {
                float a[8];
                *(float4*)&a[0] = *(const float4*)&As[kk * 128 + ty * 4];
                *(float4*)&a[4] = *(const float4*)&As[kk * 128 + 64 + ty * 4];
                ulonglong2 bv0 = *(const ulonglong2*)&Bs[kk * 128 + tx * 4];
                ulonglong2 bv1 = *(const ulonglong2*)&Bs[kk * 128 + 64 + tx * 4];
                #pragma unroll
                for (int i = 0; i < 8; i++) {
                    ull ad = dup2(a[i]);
                    fma2(acc2[i][0], ad, bv0.x);
                    fma2(acc2[i][1], ad, bv0.y);
                    fma2(acc2[i][2], ad, bv1.x);
                    fma2(acc2[i][3], ad, bv1.y);
                }
            }
            __syncthreads();
        }
        #pragma unroll
        for (int i = 0; i < 8; i++) {
            int rloc = (i < 4) ? (ty * 4 + i) : (64 + ty * 4 + i - 4);
            size_t row = (size_t)m0 + rloc;
            #pragma unroll
            for (int jp = 0; jp < 4; jp++) {
                int v0 = n0 + ((jp < 2) ? (tx * 4 + jp * 2) : (64 + tx * 4 + (jp - 2) * 2));
                float lo = __uint_as_float((unsigned)acc2[i][jp]);
                float hi = __uint_as_float((unsigned)(acc2[i][jp] >> 32));
                if (v0 < V_)     out[row * V_ + v0]     = lo + by[v0];
                if (v0 + 1 < V_) out[row * V_ + v0 + 1] = hi + by[v0 + 1];
            }
        }
    }
}

// ---------------- fused kernel ----------------
__global__ void __launch_bounds__(TPB)
fused_kernel(const float* __restrict__ Wr0, const float* __restrict__ Wz0,
             const float* __restrict__ Wh0,
             const float* __restrict__ Wr1, const float* __restrict__ Wz1,
             const float* __restrict__ Wh1,
             const float* __restrict__ br1, const float* __restrict__ bz1,
             const float* __restrict__ bh1,
             const float* __restrict__ Wy, const float* __restrict__ by,
             float* __restrict__ out) {
    extern __shared__ float sm[];
    if (blockIdx.x < NB) {
        recurrence_role(sm, Wr0, Wz0, Wh0, Wr1, Wz1, Wh1, br1, bz1, bh1);
        __syncthreads();
    }
    logits_role(sm, Wy, by, out);
}

// ---------------- launch ----------------
extern "C" void kernel_launch(void* const* d_in, const int* in_sizes, int n_in,
                              void* d_out, int out_size) {
    const int*   inputs = (const int*)d_in[0];
    const float* hidden = (const float*)d_in[1];
    const float* emb    = (const float*)d_in[2];
    const float* W_r0 = (const float*)d_in[3];
    const float* b_r0 = (const float*)d_in[4];
    const float* W_z0 = (const float*)d_in[5];
    const float* b_z0 = (const float*)d_in[6];
    const float* W_h0 = (const float*)d_in[7];
    const float* b_h0 = (const float*)d_in[8];
    const float* W_r1 = (const float*)d_in[9];
    const float* b_r1 = (const float*)d_in[10];
    const float* W_z1 = (const float*)d_in[11];
    const float* b_z1 = (const float*)d_in[12];
    const float* W_h1 = (const float*)d_in[13];
    const float* b_h1 = (const float*)d_in[14];
    const float* Wy   = (const float*)d_in[15];
    const float* by   = (const float*)d_in[16];
    float* out = (float*)d_out;

    cudaFuncSetAttribute(fused_kernel, cudaFuncAttributeMaxDynamicSharedMemorySize,
                         SMEM_BYTES);

    xproj_gemm<<<dim3(3 * H_ / 128, (S_ * B_) / 128), 256>>>(inputs, emb, W_r0, W_z0, W_h0,
                                                             b_r0, b_z0, b_h0);
    init_hidden_kernel<<<(B_ * H_ + 255) / 256, 256>>>(hidden);
    dummy_mark<<<1, 32>>>();      // shifts fused_kernel to the ncu-captured slot
    fused_kernel<<<NCTA, TPB, SMEM_BYTES>>>(W_r0, W_z0, W_h0, W_r1, W_z1, W_h1,
                                            b_r1, b_z1, b_h1, Wy, by, out);

    long long logits_elems = (long long)S_ * B_ * V_;
    if ((long long)out_size >= logits_elems + 2LL * B_ * H_) {
        write_hidden_kernel<<<(B_ * H_ + 255) / 256, 256>>>(out, logits_elems);
    }
}